// round 11
// baseline (speedup 1.0000x reference)
#include <cuda_runtime.h>
#include <cstdint>

#define Bb   2
#define Nn   2048
#define Cc   512
#define Hh   8
#define HD   64
#define BH   16
#define KTOP 1024
#define SCALEF 0.125f
#define JSPLIT 4
#define JLEN  (Nn / JSPLIT)     // 512

// ---------------- scratch ----------------
__device__ float g_Qh[BH * Nn * HD];
__device__ float g_Kh[BH * Nn * HD];
__device__ float g_Vh[BH * Nn * HD];
__device__ float g_attn[(size_t)BH * Nn * Nn];
__device__ float g_attnT[(size_t)BH * Nn * Nn];
__device__ float g_rth[BH * Nn];
__device__ float g_cth[BH * Nn];
__device__ float g_rmax[BH * Nn];
__device__ float g_O[BH * Nn * HD];
__device__ float g_Opart[(size_t)JSPLIT * BH * Nn * HD];   // 32MB
__device__ float g_dpart[JSPLIT * BH * Nn];

// ---------------- tf32 helpers ----------------
__device__ __forceinline__ unsigned tf32_rna(float x) {
    unsigned u; asm("cvt.rna.tf32.f32 %0, %1;" : "=r"(u) : "f"(x)); return u;
}
__device__ __forceinline__ void split_tf32(float x, unsigned& hi, unsigned& lo) {
    hi = tf32_rna(x);
    float hf = __uint_as_float(hi);
    lo = tf32_rna(x - hf);
}
__device__ __forceinline__ void mma_tf32(float* c, const unsigned* a, const unsigned* b) {
    asm("mma.sync.aligned.m16n8k8.row.col.f32.tf32.tf32.f32 "
        "{%0,%1,%2,%3},{%4,%5,%6,%7},{%8,%9},{%0,%1,%2,%3};"
        : "+f"(c[0]), "+f"(c[1]), "+f"(c[2]), "+f"(c[3])
        : "r"(a[0]), "r"(a[1]), "r"(a[2]), "r"(a[3]), "r"(b[0]), "r"(b[1]));
}

// ---------------------------------------------------------------------------
// Kernel 1: ALL THREE projections in one launch (grid.z = which).  (R10 exact)
// ---------------------------------------------------------------------------
__global__ __launch_bounds__(128) void proj_kernel(const float* __restrict__ q,
                                                   const float* __restrict__ k_v,
                                                   const float* __restrict__ Wq,
                                                   const float* __restrict__ Wk,
                                                   const float* __restrict__ Wv) {
    __shared__ float As[128][33];
    __shared__ float Bs[64][33];
    int which = blockIdx.z;
    const float* X = (which == 0) ? q : k_v;
    const float* W = (which == 0) ? Wq : ((which == 1) ? Wk : Wv);
    int tid = threadIdx.x;
    int tx = tid & 7, ty = tid >> 3;
    int m0 = blockIdx.y * 128, n0 = blockIdx.x * 64;
    float acc[8][8] = {};
    for (int k0 = 0; k0 < Cc; k0 += 32) {
#pragma unroll
        for (int l = tid; l < 1024; l += 128) {
            int m = l >> 3, c = (l & 7) * 4;
            float4 v = *(const float4*)&X[(size_t)(m0 + m) * Cc + k0 + c];
            As[m][c] = v.x; As[m][c + 1] = v.y; As[m][c + 2] = v.z; As[m][c + 3] = v.w;
        }
#pragma unroll
        for (int l = tid; l < 512; l += 128) {
            int n = l >> 3, c = (l & 7) * 4;
            float4 v = *(const float4*)&W[(size_t)(n0 + n) * Cc + k0 + c];
            Bs[n][c] = v.x; Bs[n][c + 1] = v.y; Bs[n][c + 2] = v.z; Bs[n][c + 3] = v.w;
        }
        __syncthreads();
#pragma unroll
        for (int kk = 0; kk < 32; kk++) {
            float a[8], b[8];
#pragma unroll
            for (int i = 0; i < 8; i++) a[i] = As[8 * ty + i][kk];
#pragma unroll
            for (int j = 0; j < 8; j++) b[j] = Bs[8 * tx + j][kk];
#pragma unroll
            for (int i = 0; i < 8; i++)
#pragma unroll
                for (int j = 0; j < 8; j++) acc[i][j] += a[i] * b[j];
        }
        __syncthreads();
    }
    float* out = (which == 0) ? g_Qh : ((which == 1) ? g_Kh : g_Vh);
#pragma unroll
    for (int i = 0; i < 8; i++) {
        int m = m0 + 8 * ty + i;
        int bb = m >> 11, nl = m & (Nn - 1);
#pragma unroll
        for (int j = 0; j < 8; j++) {
            int n = n0 + 8 * tx + j;
            int h = n >> 6, d = n & 63;
            out[(((size_t)(bb * Hh + h)) * Nn + nl) * HD + d] = acc[i][j];
        }
    }
}

// ---------------------------------------------------------------------------
// Kernel 2: attn = scale * Q K^T via 3xTF32 mma.sync   (R4 exact)
// ---------------------------------------------------------------------------
__global__ __launch_bounds__(256) void qk_tc_kernel() {
    __shared__ float Qs[128][68];
    __shared__ float Ks[32][68];
    float (*Ts)[36] = (float(*)[36])Qs;

    int tid = threadIdx.x;
    int wid = tid >> 5, lane = tid & 31;
    int g = lane >> 2, t = lane & 3;
    int wm = wid & 3, wn = wid >> 2;
    int bh = blockIdx.z;
    int i0 = blockIdx.y * 128, j0 = blockIdx.x * 32;
    const float* Q = g_Qh + (size_t)bh * Nn * HD;
    const float* K = g_Kh + (size_t)bh * Nn * HD;

#pragma unroll
    for (int p = 0; p < 8; p++) {
        int idx = p * 256 + tid;
        int m = idx >> 4, c = (idx & 15) * 4;
        float4 v = *(const float4*)&Q[(size_t)(i0 + m) * HD + c];
        *(float4*)&Qs[m][c] = v;
    }
#pragma unroll
    for (int p = 0; p < 2; p++) {
        int idx = p * 256 + tid;
        int n = idx >> 4, c = (idx & 15) * 4;
        float4 v = *(const float4*)&K[(size_t)(j0 + n) * HD + c];
        *(float4*)&Ks[n][c] = v;
    }
    __syncthreads();

    float acc[2][2][4] = {};
#pragma unroll
    for (int ks = 0; ks < 8; ks++) {
        int k0 = ks * 8;
        unsigned ahi[2][4], alo[2][4], bhi[2][2], blo[2][2];
#pragma unroll
        for (int mt = 0; mt < 2; mt++) {
            int rb = 32 * wm + 16 * mt;
            float x0 = Qs[rb + g][k0 + t];
            float x1 = Qs[rb + g + 8][k0 + t];
            float x2 = Qs[rb + g][k0 + t + 4];
            float x3 = Qs[rb + g + 8][k0 + t + 4];
            split_tf32(x0, ahi[mt][0], alo[mt][0]);
            split_tf32(x1, ahi[mt][1], alo[mt][1]);
            split_tf32(x2, ahi[mt][2], alo[mt][2]);
            split_tf32(x3, ahi[mt][3], alo[mt][3]);
        }
#pragma unroll
        for (int nt = 0; nt < 2; nt++) {
            int nb = 16 * wn + 8 * nt;
            float y0 = Ks[nb + g][k0 + t];
            float y1 = Ks[nb + g][k0 + t + 4];
            split_tf32(y0, bhi[nt][0], blo[nt][0]);
            split_tf32(y1, bhi[nt][1], blo[nt][1]);
        }
#pragma unroll
        for (int mt = 0; mt < 2; mt++)
#pragma unroll
            for (int nt = 0; nt < 2; nt++) {
                mma_tf32(acc[mt][nt], ahi[mt], blo[nt]);
                mma_tf32(acc[mt][nt], alo[mt], bhi[nt]);
                mma_tf32(acc[mt][nt], ahi[mt], bhi[nt]);
            }
    }
    __syncthreads();

#pragma unroll
    for (int mt = 0; mt < 2; mt++)
#pragma unroll
        for (int nt = 0; nt < 2; nt++) {
            int r0 = 32 * wm + 16 * mt + g;
            int c0 = 16 * wn + 8 * nt + 2 * t;
            Ts[r0][c0]         = acc[mt][nt][0] * SCALEF;
            Ts[r0][c0 + 1]     = acc[mt][nt][1] * SCALEF;
            Ts[r0 + 8][c0]     = acc[mt][nt][2] * SCALEF;
            Ts[r0 + 8][c0 + 1] = acc[mt][nt][3] * SCALEF;
        }
    __syncthreads();

    float* attn = g_attn + ((size_t)bh * Nn + i0) * Nn + j0;
#pragma unroll
    for (int p = 0; p < 4; p++) {
        int idx = p * 256 + tid;
        int r = idx >> 3, cq = (idx & 7) * 4;
        *(float4*)&attn[(size_t)r * Nn + cq] = *(const float4*)&Ts[r][cq];
    }
    float* attnT = g_attnT + ((size_t)bh * Nn + j0) * Nn + i0;
#pragma unroll
    for (int p = 0; p < 16; p++) {
        int idx = p * 256 + tid;
        int jl = idx >> 7, il = idx & 127;
        attnT[(size_t)jl * Nn + il] = Ts[il][jl];
    }
}

// ---------------------------------------------------------------------------
// Kernel 3: exact K_TOP-th largest per row (radix select).
// R4 algorithm; row load now 2x LDG.128 per thread (element->thread
// assignment is arbitrary for a histogram select).
// ---------------------------------------------------------------------------
__global__ __launch_bounds__(256) void select_kernel() {
    __shared__ unsigned hist[4][256];
    __shared__ unsigned S[257];
    __shared__ unsigned s_sel, s_maxu;
    int tid = threadIdx.x;
    size_t row = blockIdx.x;
    int dir = blockIdx.y;
    const float* src = (dir ? g_attnT : g_attn) + row * Nn;

    unsigned u[8], lmax = 0u;
    {
        float4 v0 = *(const float4*)&src[tid * 8];
        float4 v1 = *(const float4*)&src[tid * 8 + 4];
        float vals[8] = {v0.x, v0.y, v0.z, v0.w, v1.x, v1.y, v1.z, v1.w};
#pragma unroll
        for (int r = 0; r < 8; r++) {
            unsigned b = __float_as_uint(vals[r]);
            u[r] = b ^ ((unsigned)((int)b >> 31) | 0x80000000u);
            lmax = lmax > u[r] ? lmax : u[r];
        }
    }
    if (tid == 0) s_maxu = 0u;

    unsigned prefix = 0u;
    int krem = KTOP;
    int hb = tid >> 6;
#pragma unroll
    for (int pass = 0; pass < 4; pass++) {
        int shift = 24 - 8 * pass;
        hist[0][tid] = 0u; hist[1][tid] = 0u; hist[2][tid] = 0u; hist[3][tid] = 0u;
        __syncthreads();
        if (pass == 0) atomicMax(&s_maxu, lmax);
        unsigned himask = (pass == 0) ? 0u : (0xFFFFFFFFu << (shift + 8));
#pragma unroll
        for (int r = 0; r < 8; r++)
            if ((u[r] & himask) == prefix)
                atomicAdd(&hist[hb][(u[r] >> shift) & 255u], 1u);
        __syncthreads();
        unsigned h = hist[0][tid] + hist[1][tid] + hist[2][tid] + hist[3][tid];
        hist[0][tid] = h;
        __syncthreads();
        if (tid < 32) {
            int base = tid * 8;
            unsigned c[8], loc[8];
#pragma unroll
            for (int j = 0; j < 8; j++) c[j] = hist[0][base + j];
            loc[7] = c[7];
#pragma unroll
            for (int j = 6; j >= 0; j--) loc[j] = c[j] + loc[j + 1];
            unsigned T = loc[0], incl = T;
#pragma unroll
            for (int off = 1; off < 32; off <<= 1) {
                unsigned v = __shfl_down_sync(0xFFFFFFFFu, incl, off);
                if (tid + off < 32) incl += v;
            }
            unsigned excl = incl - T;
#pragma unroll
            for (int j = 0; j < 8; j++) S[base + j] = excl + loc[j];
            if (tid == 0) S[256] = 0u;
        }
        __syncthreads();
        unsigned St = S[tid], St1 = S[tid + 1];
        if ((int)St >= krem && (int)St1 < krem) s_sel = (unsigned)tid;
        __syncthreads();
        unsigned sel = s_sel;
        krem -= (int)S[sel + 1];
        prefix |= sel << shift;
        __syncthreads();
    }
    if (tid == 0) {
        unsigned b = (prefix & 0x80000000u) ? (prefix ^ 0x80000000u) : ~prefix;
        float thr = __uint_as_float(b);
        if (dir) {
            g_cth[row] = thr;
        } else {
            g_rth[row] = thr;
            unsigned um = s_maxu;
            unsigned bm = (um & 0x80000000u) ? (um ^ 0x80000000u) : ~um;
            g_rmax[row] = __uint_as_float(bm);
        }
    }
}

// ---------------------------------------------------------------------------
// Kernel 4: fused masked softmax + P@V, J-SPLIT partials.
// 256 threads, 4 rows x 8 cols per thread (register relief: acc 32 regs).
// Same m-major Ps / Vs layout as the proven 128-thread version.
// grid (Nn/128, JSPLIT, BH), block 256.
// ---------------------------------------------------------------------------
__global__ __launch_bounds__(256) void spv_part_kernel() {
    __shared__ float Ps[128][33];
    __shared__ float Vs[32][68];
    __shared__ float s_rth[128], s_mx[128], s_cth[32], s_den[128];
    int tid = threadIdx.x;
    int tx = tid & 7, ty = tid >> 3;      // ty 0..31
    int bh = blockIdx.z;
    int part = blockIdx.y;
    int js = part * JLEN;
    int i0 = blockIdx.x * 128;
    const float* V = g_Vh + (size_t)bh * Nn * HD;
    const float* A = g_attn + ((size_t)bh * Nn + i0) * Nn;
    if (tid < 128) {
        s_rth[tid] = g_rth[bh * Nn + i0 + tid];
        s_mx[tid]  = g_rmax[bh * Nn + i0 + tid];
    }
    __syncthreads();
    float rthr[4], mr[4], dloc[4];
#pragma unroll
    for (int i = 0; i < 4; i++) {
        rthr[i] = s_rth[4 * ty + i];
        mr[i]   = s_mx[4 * ty + i];
        dloc[i] = 0.f;
    }
    float acc[4][8] = {};

    for (int j0 = js; j0 < js + JLEN; j0 += 32) {
        float4 araw[4];
#pragma unroll
        for (int i = 0; i < 4; i++)
            araw[i] = *(const float4*)&A[(size_t)(4 * ty + i) * Nn + j0 + 4 * tx];
        __syncthreads();                  // prev chunk MMA done
        if (tid < 32) s_cth[tid] = g_cth[bh * Nn + j0 + tid];
#pragma unroll
        for (int p = 0; p < 2; p++) {     // V chunk 32x64
            int idx = p * 256 + tid;
            int jl = idx >> 4, d = (idx & 15) * 4;
            *(float4*)&Vs[jl][d] = *(const float4*)&V[(size_t)(j0 + jl) * HD + d];
        }
        __syncthreads();                  // cth + Vs visible
#pragma unroll
        for (int i = 0; i < 4; i++) {
            float av[4] = {araw[i].x, araw[i].y, araw[i].z, araw[i].w};
#pragma unroll
            for (int uu = 0; uu < 4; uu++) {
                float a = av[uu];
                float thr = fminf(rthr[i], s_cth[4 * tx + uu]);
                float p = (a >= thr) ? __expf(a - mr[i]) : 0.f;
                dloc[i] += p;
                Ps[4 * ty + i][4 * tx + uu] = p;
            }
        }
        __syncthreads();                  // Ps complete
#pragma unroll
        for (int kk = 0; kk < 32; kk++) {
            float a[4], b[8];
#pragma unroll
            for (int i = 0; i < 4; i++) a[i] = Ps[4 * ty + i][kk];
            float4 b0 = *(const float4*)&Vs[kk][8 * tx];
            float4 b1 = *(const float4*)&Vs[kk][8 * tx + 4];
            b[0] = b0.x; b[1] = b0.y; b[2] = b0.z; b[3] = b0.w;
            b[4] = b1.x; b[5] = b1.y; b[6] = b1.z; b[7] = b1.w;
#pragma unroll
            for (int i = 0; i < 4; i++)
#pragma unroll
                for (int j = 0; j < 8; j++) acc[i][j] += a[i] * b[j];
        }
    }
    // deterministic denominator: 8 tx-lanes share row 4*ty+i
#pragma unroll
    for (int i = 0; i < 4; i++) {
        dloc[i] += __shfl_xor_sync(0xFFFFFFFFu, dloc[i], 1);
        dloc[i] += __shfl_xor_sync(0xFFFFFFFFu, dloc[i], 2);
        dloc[i] += __shfl_xor_sync(0xFFFFFFFFu, dloc[i], 4);
    }
    if (tx == 0) {
#pragma unroll
        for (int i = 0; i < 4; i++) s_den[4 * ty + i] = dloc[i];
    }
    __syncthreads();
    if (tid < 128) {
        size_t rowg = (size_t)bh * Nn + i0 + tid;
        g_dpart[(size_t)part * BH * Nn + rowg] = s_den[tid];
    }
    float* Op = g_Opart + (size_t)part * BH * Nn * HD;
#pragma unroll
    for (int i = 0; i < 4; i++) {
        int il = 4 * ty + i;
        float4 v0 = make_float4(acc[i][0], acc[i][1], acc[i][2], acc[i][3]);
        float4 v1 = make_float4(acc[i][4], acc[i][5], acc[i][6], acc[i][7]);
        float* o = &Op[((size_t)bh * Nn + i0 + il) * HD + 8 * tx];
        *(float4*)o = v0;
        *(float4*)(o + 4) = v1;
    }
}

// ---------------------------------------------------------------------------
// Kernel 4b: merge partials -> g_O.  (R10 exact)
// ---------------------------------------------------------------------------
__global__ __launch_bounds__(256) void spv_merge_kernel() {
    int gid = blockIdx.x * 256 + threadIdx.x;
    size_t row = (size_t)gid >> 4;
    int dd = (gid & 15) * 4;
    float den = g_dpart[row] + g_dpart[BH * Nn + row]
              + g_dpart[2 * BH * Nn + row] + g_dpart[3 * BH * Nn + row];
    float inv = 1.f / den;
    size_t base = row * HD + dd;
    float4 s0 = *(const float4*)&g_Opart[base];
    float4 s1 = *(const float4*)&g_Opart[(size_t)BH * Nn * HD + base];
    float4 s2 = *(const float4*)&g_Opart[2 * (size_t)BH * Nn * HD + base];
    float4 s3 = *(const float4*)&g_Opart[3 * (size_t)BH * Nn * HD + base];
    float4 r;
    r.x = (s0.x + s1.x + s2.x + s3.x) * inv;
    r.y = (s0.y + s1.y + s2.y + s3.y) * inv;
    r.z = (s0.z + s1.z + s2.z + s3.z) * inv;
    r.w = (s0.w + s1.w + s2.w + s3.w) * inv;
    *(float4*)&g_O[base] = r;
}

// ---------------------------------------------------------------------------
// Kernel 5: output projection   (R4 exact)
// ---------------------------------------------------------------------------
__global__ __launch_bounds__(128) void outproj_kernel(const float* __restrict__ Wp,
                                                      const float* __restrict__ bp,
                                                      float* __restrict__ out) {
    __shared__ float As[128][33];
    __shared__ float Bs[64][33];
    int tid = threadIdx.x;
    int tx = tid & 7, ty = tid >> 3;
    int m0 = blockIdx.y * 128, n0 = blockIdx.x * 64;
    float acc[8][8] = {};
    for (int k0 = 0; k0 < Cc; k0 += 32) {
        int h = k0 >> 6;
#pragma unroll
        for (int l = tid; l < 1024; l += 128) {
            int m = l >> 3, c = (l & 7) * 4;
            int mg = m0 + m;
            int bb = mg >> 11, nl = mg & (Nn - 1);
            int d = (k0 + c) & 63;
            float4 v = *(const float4*)&g_O[(((size_t)(bb * Hh + h)) * Nn + nl) * HD + d];
            As[m][c] = v.x; As[m][c + 1] = v.y; As[m][c + 2] = v.z; As[m][c + 3] = v.w;
        }
#pragma unroll
        for (int l = tid; l < 512; l += 128) {
            int n = l >> 3, c = (l & 7) * 4;
            float4 v = *(const float4*)&Wp[(size_t)(n0 + n) * Cc + k0 + c];
            Bs[n][c] = v.x; Bs[n][c + 1] = v.y; Bs[n][c + 2] = v.z; Bs[n][c + 3] = v.w;
        }
        __syncthreads();
#pragma unroll
        for (int kk = 0; kk < 32; kk++) {
            float a[8], b[8];
#pragma unroll
            for (int i = 0; i < 8; i++) a[i] = As[8 * ty + i][kk];
#pragma unroll
            for (int j = 0; j < 8; j++) b[j] = Bs[8 * tx + j][kk];
#pragma unroll
            for (int i = 0; i < 8; i++)
#pragma unroll
                for (int j = 0; j < 8; j++) acc[i][j] += a[i] * b[j];
        }
        __syncthreads();
    }
#pragma unroll
    for (int i = 0; i < 8; i++) {
        int m = m0 + 8 * ty + i;
#pragma unroll
        for (int j = 0; j < 8; j++) {
            int n = n0 + 8 * tx + j;
            out[(size_t)m * Cc + n] = acc[i][j] + bp[n];
        }
    }
}

// ---------------------------------------------------------------------------
extern "C" void kernel_launch(void* const* d_in, const int* in_sizes, int n_in,
                              void* d_out, int out_size) {
    (void)in_sizes; (void)n_in; (void)out_size;
    const float* q   = (const float*)d_in[0];
    const float* k_v = (const float*)d_in[1];
    const float* Wq  = (const float*)d_in[2];
    const float* Wk  = (const float*)d_in[3];
    const float* Wv  = (const float*)d_in[4];
    const float* Wp  = (const float*)d_in[5];
    const float* bp  = (const float*)d_in[6];
    float* out = (float*)d_out;

    dim3 gproj(Cc / 64, (Bb * Nn) / 128, 3);           // (8, 32, 3)
    proj_kernel<<<gproj, 128>>>(q, k_v, Wq, Wk, Wv);

    dim3 gqk(Nn / 32, Nn / 128, BH);                   // (64, 16, 16)
    qk_tc_kernel<<<gqk, 256>>>();

    dim3 gsel(BH * Nn, 2);
    select_kernel<<<gsel, 256>>>();

    dim3 gspv(Nn / 128, JSPLIT, BH);                   // (16, 4, 16)
    spv_part_kernel<<<gspv, 256>>>();

    spv_merge_kernel<<<(BH * Nn * HD / 4) / 256, 256>>>();

    dim3 gout(Cc / 64, (Bb * Nn) / 128);
    outproj_kernel<<<gout, 128>>>(Wp, bp, out);
}

// round 12
// speedup vs baseline: 1.0303x; 1.0303x over previous
#include <cuda_runtime.h>
#include <cstdint>

#define Bb   2
#define Nn   2048
#define Cc   512
#define Hh   8
#define HD   64
#define BH   16
#define KTOP 1024
#define SCALEF 0.125f
#define JSPLIT 4
#define JLEN  (Nn / JSPLIT)     // 512

// ---------------- scratch ----------------
__device__ float g_Qh[BH * Nn * HD];
__device__ float g_Kh[BH * Nn * HD];
__device__ float g_Vh[BH * Nn * HD];
__device__ float g_attn[(size_t)BH * Nn * Nn];
__device__ float g_attnT[(size_t)BH * Nn * Nn];
__device__ float g_rth[BH * Nn];
__device__ float g_cth[BH * Nn];
__device__ float g_rmax[BH * Nn];
__device__ float g_O[BH * Nn * HD];
__device__ float g_Opart[(size_t)JSPLIT * BH * Nn * HD];   // 32MB
__device__ float g_dpart[JSPLIT * BH * Nn];

// ---------------- tf32 helpers ----------------
__device__ __forceinline__ unsigned tf32_rna(float x) {
    unsigned u; asm("cvt.rna.tf32.f32 %0, %1;" : "=r"(u) : "f"(x)); return u;
}
__device__ __forceinline__ void split_tf32(float x, unsigned& hi, unsigned& lo) {
    hi = tf32_rna(x);
    float hf = __uint_as_float(hi);
    lo = tf32_rna(x - hf);
}
__device__ __forceinline__ void mma_tf32(float* c, const unsigned* a, const unsigned* b) {
    asm("mma.sync.aligned.m16n8k8.row.col.f32.tf32.tf32.f32 "
        "{%0,%1,%2,%3},{%4,%5,%6,%7},{%8,%9},{%0,%1,%2,%3};"
        : "+f"(c[0]), "+f"(c[1]), "+f"(c[2]), "+f"(c[3])
        : "r"(a[0]), "r"(a[1]), "r"(a[2]), "r"(a[3]), "r"(b[0]), "r"(b[1]));
}

// ---------------------------------------------------------------------------
// Kernel 1: ALL THREE projections in one launch (grid.z = which).  (R10 exact)
// ---------------------------------------------------------------------------
__global__ __launch_bounds__(128) void proj_kernel(const float* __restrict__ q,
                                                   const float* __restrict__ k_v,
                                                   const float* __restrict__ Wq,
                                                   const float* __restrict__ Wk,
                                                   const float* __restrict__ Wv) {
    __shared__ float As[128][33];
    __shared__ float Bs[64][33];
    int which = blockIdx.z;
    const float* X = (which == 0) ? q : k_v;
    const float* W = (which == 0) ? Wq : ((which == 1) ? Wk : Wv);
    int tid = threadIdx.x;
    int tx = tid & 7, ty = tid >> 3;
    int m0 = blockIdx.y * 128, n0 = blockIdx.x * 64;
    float acc[8][8] = {};
    for (int k0 = 0; k0 < Cc; k0 += 32) {
#pragma unroll
        for (int l = tid; l < 1024; l += 128) {
            int m = l >> 3, c = (l & 7) * 4;
            float4 v = *(const float4*)&X[(size_t)(m0 + m) * Cc + k0 + c];
            As[m][c] = v.x; As[m][c + 1] = v.y; As[m][c + 2] = v.z; As[m][c + 3] = v.w;
        }
#pragma unroll
        for (int l = tid; l < 512; l += 128) {
            int n = l >> 3, c = (l & 7) * 4;
            float4 v = *(const float4*)&W[(size_t)(n0 + n) * Cc + k0 + c];
            Bs[n][c] = v.x; Bs[n][c + 1] = v.y; Bs[n][c + 2] = v.z; Bs[n][c + 3] = v.w;
        }
        __syncthreads();
#pragma unroll
        for (int kk = 0; kk < 32; kk++) {
            float a[8], b[8];
#pragma unroll
            for (int i = 0; i < 8; i++) a[i] = As[8 * ty + i][kk];
#pragma unroll
            for (int j = 0; j < 8; j++) b[j] = Bs[8 * tx + j][kk];
#pragma unroll
            for (int i = 0; i < 8; i++)
#pragma unroll
                for (int j = 0; j < 8; j++) acc[i][j] += a[i] * b[j];
        }
        __syncthreads();
    }
    float* out = (which == 0) ? g_Qh : ((which == 1) ? g_Kh : g_Vh);
#pragma unroll
    for (int i = 0; i < 8; i++) {
        int m = m0 + 8 * ty + i;
        int bb = m >> 11, nl = m & (Nn - 1);
#pragma unroll
        for (int j = 0; j < 8; j++) {
            int n = n0 + 8 * tx + j;
            int h = n >> 6, d = n & 63;
            out[(((size_t)(bb * Hh + h)) * Nn + nl) * HD + d] = acc[i][j];
        }
    }
}

// ---------------------------------------------------------------------------
// Kernel 2: attn = scale * Q K^T via 3xTF32 mma.sync   (R4 exact)
// ---------------------------------------------------------------------------
__global__ __launch_bounds__(256) void qk_tc_kernel() {
    __shared__ float Qs[128][68];
    __shared__ float Ks[32][68];
    float (*Ts)[36] = (float(*)[36])Qs;

    int tid = threadIdx.x;
    int wid = tid >> 5, lane = tid & 31;
    int g = lane >> 2, t = lane & 3;
    int wm = wid & 3, wn = wid >> 2;
    int bh = blockIdx.z;
    int i0 = blockIdx.y * 128, j0 = blockIdx.x * 32;
    const float* Q = g_Qh + (size_t)bh * Nn * HD;
    const float* K = g_Kh + (size_t)bh * Nn * HD;

#pragma unroll
    for (int p = 0; p < 8; p++) {
        int idx = p * 256 + tid;
        int m = idx >> 4, c = (idx & 15) * 4;
        float4 v = *(const float4*)&Q[(size_t)(i0 + m) * HD + c];
        *(float4*)&Qs[m][c] = v;
    }
#pragma unroll
    for (int p = 0; p < 2; p++) {
        int idx = p * 256 + tid;
        int n = idx >> 4, c = (idx & 15) * 4;
        float4 v = *(const float4*)&K[(size_t)(j0 + n) * HD + c];
        *(float4*)&Ks[n][c] = v;
    }
    __syncthreads();

    float acc[2][2][4] = {};
#pragma unroll
    for (int ks = 0; ks < 8; ks++) {
        int k0 = ks * 8;
        unsigned ahi[2][4], alo[2][4], bhi[2][2], blo[2][2];
#pragma unroll
        for (int mt = 0; mt < 2; mt++) {
            int rb = 32 * wm + 16 * mt;
            float x0 = Qs[rb + g][k0 + t];
            float x1 = Qs[rb + g + 8][k0 + t];
            float x2 = Qs[rb + g][k0 + t + 4];
            float x3 = Qs[rb + g + 8][k0 + t + 4];
            split_tf32(x0, ahi[mt][0], alo[mt][0]);
            split_tf32(x1, ahi[mt][1], alo[mt][1]);
            split_tf32(x2, ahi[mt][2], alo[mt][2]);
            split_tf32(x3, ahi[mt][3], alo[mt][3]);
        }
#pragma unroll
        for (int nt = 0; nt < 2; nt++) {
            int nb = 16 * wn + 8 * nt;
            float y0 = Ks[nb + g][k0 + t];
            float y1 = Ks[nb + g][k0 + t + 4];
            split_tf32(y0, bhi[nt][0], blo[nt][0]);
            split_tf32(y1, bhi[nt][1], blo[nt][1]);
        }
#pragma unroll
        for (int mt = 0; mt < 2; mt++)
#pragma unroll
            for (int nt = 0; nt < 2; nt++) {
                mma_tf32(acc[mt][nt], ahi[mt], blo[nt]);
                mma_tf32(acc[mt][nt], alo[mt], bhi[nt]);
                mma_tf32(acc[mt][nt], ahi[mt], bhi[nt]);
            }
    }
    __syncthreads();

#pragma unroll
    for (int mt = 0; mt < 2; mt++)
#pragma unroll
        for (int nt = 0; nt < 2; nt++) {
            int r0 = 32 * wm + 16 * mt + g;
            int c0 = 16 * wn + 8 * nt + 2 * t;
            Ts[r0][c0]         = acc[mt][nt][0] * SCALEF;
            Ts[r0][c0 + 1]     = acc[mt][nt][1] * SCALEF;
            Ts[r0 + 8][c0]     = acc[mt][nt][2] * SCALEF;
            Ts[r0 + 8][c0 + 1] = acc[mt][nt][3] * SCALEF;
        }
    __syncthreads();

    float* attn = g_attn + ((size_t)bh * Nn + i0) * Nn + j0;
#pragma unroll
    for (int p = 0; p < 4; p++) {
        int idx = p * 256 + tid;
        int r = idx >> 3, cq = (idx & 7) * 4;
        *(float4*)&attn[(size_t)r * Nn + cq] = *(const float4*)&Ts[r][cq];
    }
    float* attnT = g_attnT + ((size_t)bh * Nn + j0) * Nn + i0;
#pragma unroll
    for (int p = 0; p < 16; p++) {
        int idx = p * 256 + tid;
        int jl = idx >> 7, il = idx & 127;
        attnT[(size_t)jl * Nn + il] = Ts[il][jl];
    }
}

// ---------------------------------------------------------------------------
// Kernel 3: exact K_TOP-th largest per row (radix select).
// R4 algorithm + LDG.128 row load (R11, measured ~30us win).
// ---------------------------------------------------------------------------
__global__ __launch_bounds__(256) void select_kernel() {
    __shared__ unsigned hist[4][256];
    __shared__ unsigned S[257];
    __shared__ unsigned s_sel, s_maxu;
    int tid = threadIdx.x;
    size_t row = blockIdx.x;
    int dir = blockIdx.y;
    const float* src = (dir ? g_attnT : g_attn) + row * Nn;

    unsigned u[8], lmax = 0u;
    {
        float4 v0 = *(const float4*)&src[tid * 8];
        float4 v1 = *(const float4*)&src[tid * 8 + 4];
        float vals[8] = {v0.x, v0.y, v0.z, v0.w, v1.x, v1.y, v1.z, v1.w};
#pragma unroll
        for (int r = 0; r < 8; r++) {
            unsigned b = __float_as_uint(vals[r]);
            u[r] = b ^ ((unsigned)((int)b >> 31) | 0x80000000u);
            lmax = lmax > u[r] ? lmax : u[r];
        }
    }
    if (tid == 0) s_maxu = 0u;

    unsigned prefix = 0u;
    int krem = KTOP;
    int hb = tid >> 6;
#pragma unroll
    for (int pass = 0; pass < 4; pass++) {
        int shift = 24 - 8 * pass;
        hist[0][tid] = 0u; hist[1][tid] = 0u; hist[2][tid] = 0u; hist[3][tid] = 0u;
        __syncthreads();
        if (pass == 0) atomicMax(&s_maxu, lmax);
        unsigned himask = (pass == 0) ? 0u : (0xFFFFFFFFu << (shift + 8));
#pragma unroll
        for (int r = 0; r < 8; r++)
            if ((u[r] & himask) == prefix)
                atomicAdd(&hist[hb][(u[r] >> shift) & 255u], 1u);
        __syncthreads();
        unsigned h = hist[0][tid] + hist[1][tid] + hist[2][tid] + hist[3][tid];
        hist[0][tid] = h;
        __syncthreads();
        if (tid < 32) {
            int base = tid * 8;
            unsigned c[8], loc[8];
#pragma unroll
            for (int j = 0; j < 8; j++) c[j] = hist[0][base + j];
            loc[7] = c[7];
#pragma unroll
            for (int j = 6; j >= 0; j--) loc[j] = c[j] + loc[j + 1];
            unsigned T = loc[0], incl = T;
#pragma unroll
            for (int off = 1; off < 32; off <<= 1) {
                unsigned v = __shfl_down_sync(0xFFFFFFFFu, incl, off);
                if (tid + off < 32) incl += v;
            }
            unsigned excl = incl - T;
#pragma unroll
            for (int j = 0; j < 8; j++) S[base + j] = excl + loc[j];
            if (tid == 0) S[256] = 0u;
        }
        __syncthreads();
        unsigned St = S[tid], St1 = S[tid + 1];
        if ((int)St >= krem && (int)St1 < krem) s_sel = (unsigned)tid;
        __syncthreads();
        unsigned sel = s_sel;
        krem -= (int)S[sel + 1];
        prefix |= sel << shift;
        __syncthreads();
    }
    if (tid == 0) {
        unsigned b = (prefix & 0x80000000u) ? (prefix ^ 0x80000000u) : ~prefix;
        float thr = __uint_as_float(b);
        if (dir) {
            g_cth[row] = thr;
        } else {
            g_rth[row] = thr;
            unsigned um = s_maxu;
            unsigned bm = (um & 0x80000000u) ? (um ^ 0x80000000u) : ~um;
            g_rmax[row] = __uint_as_float(bm);
        }
    }
}

// ---------------------------------------------------------------------------
// Kernel 4: fused masked softmax + P@V, J-SPLIT partials.  (R10 exact 128-thr)
// grid (Nn/128, JSPLIT, BH), block 128.
// ---------------------------------------------------------------------------
__global__ __launch_bounds__(128) void spv_part_kernel() {
    __shared__ float Ps[128][33];
    __shared__ float Vs[32][68];
    __shared__ float s_rth[128], s_mx[128], s_cth[32], s_den[128];
    int tid = threadIdx.x;
    int tx = tid & 7, ty = tid >> 3;
    int bh = blockIdx.z;
    int part = blockIdx.y;
    int js = part * JLEN;
    int i0 = blockIdx.x * 128;
    const float* V = g_Vh + (size_t)bh * Nn * HD;
    const float* A = g_attn + ((size_t)bh * Nn + i0) * Nn;
    s_rth[tid] = g_rth[bh * Nn + i0 + tid];
    s_mx[tid]  = g_rmax[bh * Nn + i0 + tid];
    s_den[tid] = 0.f;
    __syncthreads();
    float rthr[8], mr[8], dloc[8];
#pragma unroll
    for (int i = 0; i < 8; i++) {
        rthr[i] = s_rth[8 * ty + i];
        mr[i]   = s_mx[8 * ty + i];
        dloc[i] = 0.f;
    }
    float acc[8][8] = {};

    for (int j0 = js; j0 < js + JLEN; j0 += 32) {
        float4 araw[8];
#pragma unroll
        for (int i = 0; i < 8; i++)
            araw[i] = *(const float4*)&A[(size_t)(8 * ty + i) * Nn + j0 + 4 * tx];
        __syncthreads();
        if (tid < 32) s_cth[tid] = g_cth[bh * Nn + j0 + tid];
#pragma unroll
        for (int l = tid; l < 512; l += 128) {
            int jl = l >> 4, d = (l & 15) * 4;
            *(float4*)&Vs[jl][d] = *(const float4*)&V[(size_t)(j0 + jl) * HD + d];
        }
        __syncthreads();
#pragma unroll
        for (int i = 0; i < 8; i++) {
            float av[4] = {araw[i].x, araw[i].y, araw[i].z, araw[i].w};
#pragma unroll
            for (int uu = 0; uu < 4; uu++) {
                float a = av[uu];
                float thr = fminf(rthr[i], s_cth[4 * tx + uu]);
                float p = (a >= thr) ? __expf(a - mr[i]) : 0.f;
                dloc[i] += p;
                Ps[8 * ty + i][4 * tx + uu] = p;
            }
        }
        __syncthreads();
#pragma unroll
        for (int kk = 0; kk < 32; kk++) {
            float a[8], b[8];
#pragma unroll
            for (int i = 0; i < 8; i++) a[i] = Ps[8 * ty + i][kk];
            float4 b0 = *(const float4*)&Vs[kk][8 * tx];
            float4 b1 = *(const float4*)&Vs[kk][8 * tx + 4];
            b[0] = b0.x; b[1] = b0.y; b[2] = b0.z; b[3] = b0.w;
            b[4] = b1.x; b[5] = b1.y; b[6] = b1.z; b[7] = b1.w;
#pragma unroll
            for (int i = 0; i < 8; i++)
#pragma unroll
                for (int j = 0; j < 8; j++) acc[i][j] += a[i] * b[j];
        }
    }
#pragma unroll
    for (int i = 0; i < 8; i++) atomicAdd(&s_den[8 * ty + i], dloc[i]);
    __syncthreads();
    {
        size_t rowg = (size_t)bh * Nn + i0 + tid;
        g_dpart[(size_t)part * BH * Nn + rowg] = s_den[tid];
    }
    float* Op = g_Opart + (size_t)part * BH * Nn * HD;
#pragma unroll
    for (int i = 0; i < 8; i++) {
        int il = 8 * ty + i;
        float4 v0 = make_float4(acc[i][0], acc[i][1], acc[i][2], acc[i][3]);
        float4 v1 = make_float4(acc[i][4], acc[i][5], acc[i][6], acc[i][7]);
        float* o = &Op[((size_t)bh * Nn + i0 + il) * HD + 8 * tx];
        *(float4*)o = v0;
        *(float4*)(o + 4) = v1;
    }
}

// ---------------------------------------------------------------------------
// Kernel 4b: merge partials -> g_O.  (R10 exact)
// ---------------------------------------------------------------------------
__global__ __launch_bounds__(256) void spv_merge_kernel() {
    int gid = blockIdx.x * 256 + threadIdx.x;
    size_t row = (size_t)gid >> 4;
    int dd = (gid & 15) * 4;
    float den = g_dpart[row] + g_dpart[BH * Nn + row]
              + g_dpart[2 * BH * Nn + row] + g_dpart[3 * BH * Nn + row];
    float inv = 1.f / den;
    size_t base = row * HD + dd;
    float4 s0 = *(const float4*)&g_Opart[base];
    float4 s1 = *(const float4*)&g_Opart[(size_t)BH * Nn * HD + base];
    float4 s2 = *(const float4*)&g_Opart[2 * (size_t)BH * Nn * HD + base];
    float4 s3 = *(const float4*)&g_Opart[3 * (size_t)BH * Nn * HD + base];
    float4 r;
    r.x = (s0.x + s1.x + s2.x + s3.x) * inv;
    r.y = (s0.y + s1.y + s2.y + s3.y) * inv;
    r.z = (s0.z + s1.z + s2.z + s3.z) * inv;
    r.w = (s0.w + s1.w + s2.w + s3.w) * inv;
    *(float4*)&g_O[base] = r;
}

// ---------------------------------------------------------------------------
// Kernel 5: output projection   (R4 exact)
// ---------------------------------------------------------------------------
__global__ __launch_bounds__(128) void outproj_kernel(const float* __restrict__ Wp,
                                                      const float* __restrict__ bp,
                                                      float* __restrict__ out) {
    __shared__ float As[128][33];
    __shared__ float Bs[64][33];
    int tid = threadIdx.x;
    int tx = tid & 7, ty = tid >> 3;
    int m0 = blockIdx.y * 128, n0 = blockIdx.x * 64;
    float acc[8][8] = {};
    for (int k0 = 0; k0 < Cc; k0 += 32) {
        int h = k0 >> 6;
#pragma unroll
        for (int l = tid; l < 1024; l += 128) {
            int m = l >> 3, c = (l & 7) * 4;
            int mg = m0 + m;
            int bb = mg >> 11, nl = mg & (Nn - 1);
            int d = (k0 + c) & 63;
            float4 v = *(const float4*)&g_O[(((size_t)(bb * Hh + h)) * Nn + nl) * HD + d];
            As[m][c] = v.x; As[m][c + 1] = v.y; As[m][c + 2] = v.z; As[m][c + 3] = v.w;
        }
#pragma unroll
        for (int l = tid; l < 512; l += 128) {
            int n = l >> 3, c = (l & 7) * 4;
            float4 v = *(const float4*)&Wp[(size_t)(n0 + n) * Cc + k0 + c];
            Bs[n][c] = v.x; Bs[n][c + 1] = v.y; Bs[n][c + 2] = v.z; Bs[n][c + 3] = v.w;
        }
        __syncthreads();
#pragma unroll
        for (int kk = 0; kk < 32; kk++) {
            float a[8], b[8];
#pragma unroll
            for (int i = 0; i < 8; i++) a[i] = As[8 * ty + i][kk];
#pragma unroll
            for (int j = 0; j < 8; j++) b[j] = Bs[8 * tx + j][kk];
#pragma unroll
            for (int i = 0; i < 8; i++)
#pragma unroll
                for (int j = 0; j < 8; j++) acc[i][j] += a[i] * b[j];
        }
        __syncthreads();
    }
#pragma unroll
    for (int i = 0; i < 8; i++) {
        int m = m0 + 8 * ty + i;
#pragma unroll
        for (int j = 0; j < 8; j++) {
            int n = n0 + 8 * tx + j;
            out[(size_t)m * Cc + n] = acc[i][j] + bp[n];
        }
    }
}

// ---------------------------------------------------------------------------
extern "C" void kernel_launch(void* const* d_in, const int* in_sizes, int n_in,
                              void* d_out, int out_size) {
    (void)in_sizes; (void)n_in; (void)out_size;
    const float* q   = (const float*)d_in[0];
    const float* k_v = (const float*)d_in[1];
    const float* Wq  = (const float*)d_in[2];
    const float* Wk  = (const float*)d_in[3];
    const float* Wv  = (const float*)d_in[4];
    const float* Wp  = (const float*)d_in[5];
    const float* bp  = (const float*)d_in[6];
    float* out = (float*)d_out;

    dim3 gproj(Cc / 64, (Bb * Nn) / 128, 3);           // (8, 32, 3)
    proj_kernel<<<gproj, 128>>>(q, k_v, Wq, Wk, Wv);

    dim3 gqk(Nn / 32, Nn / 128, BH);                   // (64, 16, 16)
    qk_tc_kernel<<<gqk, 256>>>();

    dim3 gsel(BH * Nn, 2);
    select_kernel<<<gsel, 256>>>();

    dim3 gspv(Nn / 128, JSPLIT, BH);                   // (16, 4, 16)
    spv_part_kernel<<<gspv, 128>>>();

    spv_merge_kernel<<<(BH * Nn * HD / 4) / 256, 256>>>();

    dim3 gout(Cc / 64, (Bb * Nn) / 128);
    outproj_kernel<<<gout, 128>>>(Wp, bp, out);
}

// round 13
// speedup vs baseline: 1.0413x; 1.0107x over previous
#include <cuda_runtime.h>
#include <cstdint>

#define Bb   2
#define Nn   2048
#define Cc   512
#define Hh   8
#define HD   64
#define BH   16
#define KTOP 1024
#define SCALEF 0.125f
#define JSPLIT 4
#define JLEN  (Nn / JSPLIT)     // 512

// ---------------- scratch ----------------
__device__ float g_Qh[BH * Nn * HD];
__device__ float g_Kh[BH * Nn * HD];
__device__ float g_Vh[BH * Nn * HD];
__device__ float g_attn[(size_t)BH * Nn * Nn];
__device__ float g_attnT[(size_t)BH * Nn * Nn];
__device__ float g_rth[BH * Nn];
__device__ float g_cth[BH * Nn];
__device__ float g_rmax[BH * Nn];
__device__ float g_O[BH * Nn * HD];
__device__ float g_Opart[(size_t)JSPLIT * BH * Nn * HD];   // 32MB
__device__ float g_dpart[JSPLIT * BH * Nn];

// ---------------- tf32 helpers ----------------
__device__ __forceinline__ unsigned tf32_rna(float x) {
    unsigned u; asm("cvt.rna.tf32.f32 %0, %1;" : "=r"(u) : "f"(x)); return u;
}
__device__ __forceinline__ void split_tf32(float x, unsigned& hi, unsigned& lo) {
    hi = tf32_rna(x);
    float hf = __uint_as_float(hi);
    lo = tf32_rna(x - hf);
}
__device__ __forceinline__ void mma_tf32(float* c, const unsigned* a, const unsigned* b) {
    asm("mma.sync.aligned.m16n8k8.row.col.f32.tf32.tf32.f32 "
        "{%0,%1,%2,%3},{%4,%5,%6,%7},{%8,%9},{%0,%1,%2,%3};"
        : "+f"(c[0]), "+f"(c[1]), "+f"(c[2]), "+f"(c[3])
        : "r"(a[0]), "r"(a[1]), "r"(a[2]), "r"(a[3]), "r"(b[0]), "r"(b[1]));
}

// ---------------------------------------------------------------------------
// Kernel 1: ALL THREE projections in one launch (grid.z = which).  (R10 exact)
// ---------------------------------------------------------------------------
__global__ __launch_bounds__(128) void proj_kernel(const float* __restrict__ q,
                                                   const float* __restrict__ k_v,
                                                   const float* __restrict__ Wq,
                                                   const float* __restrict__ Wk,
                                                   const float* __restrict__ Wv) {
    __shared__ float As[128][33];
    __shared__ float Bs[64][33];
    int which = blockIdx.z;
    const float* X = (which == 0) ? q : k_v;
    const float* W = (which == 0) ? Wq : ((which == 1) ? Wk : Wv);
    int tid = threadIdx.x;
    int tx = tid & 7, ty = tid >> 3;
    int m0 = blockIdx.y * 128, n0 = blockIdx.x * 64;
    float acc[8][8] = {};
    for (int k0 = 0; k0 < Cc; k0 += 32) {
#pragma unroll
        for (int l = tid; l < 1024; l += 128) {
            int m = l >> 3, c = (l & 7) * 4;
            float4 v = *(const float4*)&X[(size_t)(m0 + m) * Cc + k0 + c];
            As[m][c] = v.x; As[m][c + 1] = v.y; As[m][c + 2] = v.z; As[m][c + 3] = v.w;
        }
#pragma unroll
        for (int l = tid; l < 512; l += 128) {
            int n = l >> 3, c = (l & 7) * 4;
            float4 v = *(const float4*)&W[(size_t)(n0 + n) * Cc + k0 + c];
            Bs[n][c] = v.x; Bs[n][c + 1] = v.y; Bs[n][c + 2] = v.z; Bs[n][c + 3] = v.w;
        }
        __syncthreads();
#pragma unroll
        for (int kk = 0; kk < 32; kk++) {
            float a[8], b[8];
#pragma unroll
            for (int i = 0; i < 8; i++) a[i] = As[8 * ty + i][kk];
#pragma unroll
            for (int j = 0; j < 8; j++) b[j] = Bs[8 * tx + j][kk];
#pragma unroll
            for (int i = 0; i < 8; i++)
#pragma unroll
                for (int j = 0; j < 8; j++) acc[i][j] += a[i] * b[j];
        }
        __syncthreads();
    }
    float* out = (which == 0) ? g_Qh : ((which == 1) ? g_Kh : g_Vh);
#pragma unroll
    for (int i = 0; i < 8; i++) {
        int m = m0 + 8 * ty + i;
        int bb = m >> 11, nl = m & (Nn - 1);
#pragma unroll
        for (int j = 0; j < 8; j++) {
            int n = n0 + 8 * tx + j;
            int h = n >> 6, d = n & 63;
            out[(((size_t)(bb * Hh + h)) * Nn + nl) * HD + d] = acc[i][j];
        }
    }
}

// ---------------------------------------------------------------------------
// Kernel 2: attn = scale * Q K^T via 3xTF32 mma.sync   (R4 exact)
// ---------------------------------------------------------------------------
__global__ __launch_bounds__(256) void qk_tc_kernel() {
    __shared__ float Qs[128][68];
    __shared__ float Ks[32][68];
    float (*Ts)[36] = (float(*)[36])Qs;

    int tid = threadIdx.x;
    int wid = tid >> 5, lane = tid & 31;
    int g = lane >> 2, t = lane & 3;
    int wm = wid & 3, wn = wid >> 2;
    int bh = blockIdx.z;
    int i0 = blockIdx.y * 128, j0 = blockIdx.x * 32;
    const float* Q = g_Qh + (size_t)bh * Nn * HD;
    const float* K = g_Kh + (size_t)bh * Nn * HD;

#pragma unroll
    for (int p = 0; p < 8; p++) {
        int idx = p * 256 + tid;
        int m = idx >> 4, c = (idx & 15) * 4;
        float4 v = *(const float4*)&Q[(size_t)(i0 + m) * HD + c];
        *(float4*)&Qs[m][c] = v;
    }
#pragma unroll
    for (int p = 0; p < 2; p++) {
        int idx = p * 256 + tid;
        int n = idx >> 4, c = (idx & 15) * 4;
        float4 v = *(const float4*)&K[(size_t)(j0 + n) * HD + c];
        *(float4*)&Ks[n][c] = v;
    }
    __syncthreads();

    float acc[2][2][4] = {};
#pragma unroll
    for (int ks = 0; ks < 8; ks++) {
        int k0 = ks * 8;
        unsigned ahi[2][4], alo[2][4], bhi[2][2], blo[2][2];
#pragma unroll
        for (int mt = 0; mt < 2; mt++) {
            int rb = 32 * wm + 16 * mt;
            float x0 = Qs[rb + g][k0 + t];
            float x1 = Qs[rb + g + 8][k0 + t];
            float x2 = Qs[rb + g][k0 + t + 4];
            float x3 = Qs[rb + g + 8][k0 + t + 4];
            split_tf32(x0, ahi[mt][0], alo[mt][0]);
            split_tf32(x1, ahi[mt][1], alo[mt][1]);
            split_tf32(x2, ahi[mt][2], alo[mt][2]);
            split_tf32(x3, ahi[mt][3], alo[mt][3]);
        }
#pragma unroll
        for (int nt = 0; nt < 2; nt++) {
            int nb = 16 * wn + 8 * nt;
            float y0 = Ks[nb + g][k0 + t];
            float y1 = Ks[nb + g][k0 + t + 4];
            split_tf32(y0, bhi[nt][0], blo[nt][0]);
            split_tf32(y1, bhi[nt][1], blo[nt][1]);
        }
#pragma unroll
        for (int mt = 0; mt < 2; mt++)
#pragma unroll
            for (int nt = 0; nt < 2; nt++) {
                mma_tf32(acc[mt][nt], ahi[mt], blo[nt]);
                mma_tf32(acc[mt][nt], alo[mt], bhi[nt]);
                mma_tf32(acc[mt][nt], ahi[mt], bhi[nt]);
            }
    }
    __syncthreads();

#pragma unroll
    for (int mt = 0; mt < 2; mt++)
#pragma unroll
        for (int nt = 0; nt < 2; nt++) {
            int r0 = 32 * wm + 16 * mt + g;
            int c0 = 16 * wn + 8 * nt + 2 * t;
            Ts[r0][c0]         = acc[mt][nt][0] * SCALEF;
            Ts[r0][c0 + 1]     = acc[mt][nt][1] * SCALEF;
            Ts[r0 + 8][c0]     = acc[mt][nt][2] * SCALEF;
            Ts[r0 + 8][c0 + 1] = acc[mt][nt][3] * SCALEF;
        }
    __syncthreads();

    float* attn = g_attn + ((size_t)bh * Nn + i0) * Nn + j0;
#pragma unroll
    for (int p = 0; p < 4; p++) {
        int idx = p * 256 + tid;
        int r = idx >> 3, cq = (idx & 7) * 4;
        *(float4*)&attn[(size_t)r * Nn + cq] = *(const float4*)&Ts[r][cq];
    }
    float* attnT = g_attnT + ((size_t)bh * Nn + j0) * Nn + i0;
#pragma unroll
    for (int p = 0; p < 16; p++) {
        int idx = p * 256 + tid;
        int jl = idx >> 7, il = idx & 127;
        attnT[(size_t)jl * Nn + il] = Ts[il][jl];
    }
}

// ---------------------------------------------------------------------------
// Kernel 3: PAIRED radix select — one block does BOTH the row-select (attn)
// and col-select (attnT) for the same row index.  128 threads per select,
// 16 elems/thread (4x LDG.128).  hist[2 sel][2 copies][256] keeps 64
// threads/copy (same serialization as before); two warp-scans run in
// parallel (warp 0 = sel 0, warp 4 = sel 1).  Barriers amortized 2x,
// block count halved.  grid (BH*Nn), block 256.
// ---------------------------------------------------------------------------
__global__ __launch_bounds__(256) void select_kernel() {
    __shared__ unsigned hist[2][2][256];
    __shared__ unsigned S[2][257];
    __shared__ unsigned s_selbin[2];
    __shared__ unsigned s_maxu;
    int tid = threadIdx.x;
    int sel = tid >> 7;           // 0: attn row, 1: attnT row
    int st  = tid & 127;
    int copy = (st >> 6) & 1;
    int lane = tid & 31;
    size_t row = blockIdx.x;
    const float* src = (sel ? g_attnT : g_attn) + row * Nn;

    unsigned u[16];
    unsigned lmax = 0u;
#pragma unroll
    for (int q = 0; q < 4; q++) {
        float4 v = *(const float4*)&src[st * 16 + 4 * q];
        float vals[4] = {v.x, v.y, v.z, v.w};
#pragma unroll
        for (int r = 0; r < 4; r++) {
            unsigned b = __float_as_uint(vals[r]);
            unsigned k = b ^ ((unsigned)((int)b >> 31) | 0x80000000u);
            u[4 * q + r] = k;
            lmax = lmax > k ? lmax : k;
        }
    }
    if (tid == 0) s_maxu = 0u;

    unsigned prefix = 0u;
    int krem = KTOP;
#pragma unroll
    for (int pass = 0; pass < 4; pass++) {
        int shift = 24 - 8 * pass;
        // clear both hists (1024 words, 4 per thread)
#pragma unroll
        for (int i = tid; i < 1024; i += 256) ((unsigned*)hist)[i] = 0u;
        __syncthreads();
        if (pass == 0 && sel == 0) atomicMax(&s_maxu, lmax);
        unsigned himask = (pass == 0) ? 0u : (0xFFFFFFFFu << (shift + 8));
#pragma unroll
        for (int r = 0; r < 16; r++)
            if ((u[r] & himask) == prefix)
                atomicAdd(&hist[sel][copy][(u[r] >> shift) & 255u], 1u);
        __syncthreads();
        // two parallel warp suffix-scans: warp 0 -> sel 0, warp 4 -> sel 1
        int wid = tid >> 5;
        if (wid == 0 || wid == 4) {
            int s = wid >> 2;
            int base = lane * 8;
            unsigned c[8], loc[8];
#pragma unroll
            for (int j = 0; j < 8; j++)
                c[j] = hist[s][0][base + j] + hist[s][1][base + j];
            loc[7] = c[7];
#pragma unroll
            for (int j = 6; j >= 0; j--) loc[j] = c[j] + loc[j + 1];
            unsigned T = loc[0], incl = T;
#pragma unroll
            for (int off = 1; off < 32; off <<= 1) {
                unsigned v = __shfl_down_sync(0xFFFFFFFFu, incl, off);
                if (lane + off < 32) incl += v;
            }
            unsigned excl = incl - T;
#pragma unroll
            for (int j = 0; j < 8; j++) S[s][base + j] = excl + loc[j];
            if (lane == 0) S[s][256] = 0u;
        }
        __syncthreads();
        // threshold-bin find: each thread checks 2 bins of its own sel
#pragma unroll
        for (int q = 0; q < 2; q++) {
            int b = 2 * st + q;
            unsigned St = S[sel][b], St1 = S[sel][b + 1];
            if ((int)St >= krem && (int)St1 < krem) s_selbin[sel] = (unsigned)b;
        }
        __syncthreads();
        unsigned selb = s_selbin[sel];
        krem -= (int)S[sel][selb + 1];
        prefix |= selb << shift;
        __syncthreads();
    }
    if (st == 0) {
        unsigned b = (prefix & 0x80000000u) ? (prefix ^ 0x80000000u) : ~prefix;
        float thr = __uint_as_float(b);
        if (sel) {
            g_cth[row] = thr;
        } else {
            g_rth[row] = thr;
            unsigned um = s_maxu;
            unsigned bm = (um & 0x80000000u) ? (um ^ 0x80000000u) : ~um;
            g_rmax[row] = __uint_as_float(bm);
        }
    }
}

// ---------------------------------------------------------------------------
// Kernel 4: fused masked softmax + P@V, J-SPLIT partials.  (R10 exact 128-thr)
// grid (Nn/128, JSPLIT, BH), block 128.
// ---------------------------------------------------------------------------
__global__ __launch_bounds__(128) void spv_part_kernel() {
    __shared__ float Ps[128][33];
    __shared__ float Vs[32][68];
    __shared__ float s_rth[128], s_mx[128], s_cth[32], s_den[128];
    int tid = threadIdx.x;
    int tx = tid & 7, ty = tid >> 3;
    int bh = blockIdx.z;
    int part = blockIdx.y;
    int js = part * JLEN;
    int i0 = blockIdx.x * 128;
    const float* V = g_Vh + (size_t)bh * Nn * HD;
    const float* A = g_attn + ((size_t)bh * Nn + i0) * Nn;
    s_rth[tid] = g_rth[bh * Nn + i0 + tid];
    s_mx[tid]  = g_rmax[bh * Nn + i0 + tid];
    s_den[tid] = 0.f;
    __syncthreads();
    float rthr[8], mr[8], dloc[8];
#pragma unroll
    for (int i = 0; i < 8; i++) {
        rthr[i] = s_rth[8 * ty + i];
        mr[i]   = s_mx[8 * ty + i];
        dloc[i] = 0.f;
    }
    float acc[8][8] = {};

    for (int j0 = js; j0 < js + JLEN; j0 += 32) {
        float4 araw[8];
#pragma unroll
        for (int i = 0; i < 8; i++)
            araw[i] = *(const float4*)&A[(size_t)(8 * ty + i) * Nn + j0 + 4 * tx];
        __syncthreads();
        if (tid < 32) s_cth[tid] = g_cth[bh * Nn + j0 + tid];
#pragma unroll
        for (int l = tid; l < 512; l += 128) {
            int jl = l >> 4, d = (l & 15) * 4;
            *(float4*)&Vs[jl][d] = *(const float4*)&V[(size_t)(j0 + jl) * HD + d];
        }
        __syncthreads();
#pragma unroll
        for (int i = 0; i < 8; i++) {
            float av[4] = {araw[i].x, araw[i].y, araw[i].z, araw[i].w};
#pragma unroll
            for (int uu = 0; uu < 4; uu++) {
                float a = av[uu];
                float thr = fminf(rthr[i], s_cth[4 * tx + uu]);
                float p = (a >= thr) ? __expf(a - mr[i]) : 0.f;
                dloc[i] += p;
                Ps[8 * ty + i][4 * tx + uu] = p;
            }
        }
        __syncthreads();
#pragma unroll
        for (int kk = 0; kk < 32; kk++) {
            float a[8], b[8];
#pragma unroll
            for (int i = 0; i < 8; i++) a[i] = Ps[8 * ty + i][kk];
            float4 b0 = *(const float4*)&Vs[kk][8 * tx];
            float4 b1 = *(const float4*)&Vs[kk][8 * tx + 4];
            b[0] = b0.x; b[1] = b0.y; b[2] = b0.z; b[3] = b0.w;
            b[4] = b1.x; b[5] = b1.y; b[6] = b1.z; b[7] = b1.w;
#pragma unroll
            for (int i = 0; i < 8; i++)
#pragma unroll
                for (int j = 0; j < 8; j++) acc[i][j] += a[i] * b[j];
        }
    }
#pragma unroll
    for (int i = 0; i < 8; i++) atomicAdd(&s_den[8 * ty + i], dloc[i]);
    __syncthreads();
    {
        size_t rowg = (size_t)bh * Nn + i0 + tid;
        g_dpart[(size_t)part * BH * Nn + rowg] = s_den[tid];
    }
    float* Op = g_Opart + (size_t)part * BH * Nn * HD;
#pragma unroll
    for (int i = 0; i < 8; i++) {
        int il = 8 * ty + i;
        float4 v0 = make_float4(acc[i][0], acc[i][1], acc[i][2], acc[i][3]);
        float4 v1 = make_float4(acc[i][4], acc[i][5], acc[i][6], acc[i][7]);
        float* o = &Op[((size_t)bh * Nn + i0 + il) * HD + 8 * tx];
        *(float4*)o = v0;
        *(float4*)(o + 4) = v1;
    }
}

// ---------------------------------------------------------------------------
// Kernel 4b: merge partials -> g_O.  (R10 exact)
// ---------------------------------------------------------------------------
__global__ __launch_bounds__(256) void spv_merge_kernel() {
    int gid = blockIdx.x * 256 + threadIdx.x;
    size_t row = (size_t)gid >> 4;
    int dd = (gid & 15) * 4;
    float den = g_dpart[row] + g_dpart[BH * Nn + row]
              + g_dpart[2 * BH * Nn + row] + g_dpart[3 * BH * Nn + row];
    float inv = 1.f / den;
    size_t base = row * HD + dd;
    float4 s0 = *(const float4*)&g_Opart[base];
    float4 s1 = *(const float4*)&g_Opart[(size_t)BH * Nn * HD + base];
    float4 s2 = *(const float4*)&g_Opart[2 * (size_t)BH * Nn * HD + base];
    float4 s3 = *(const float4*)&g_Opart[3 * (size_t)BH * Nn * HD + base];
    float4 r;
    r.x = (s0.x + s1.x + s2.x + s3.x) * inv;
    r.y = (s0.y + s1.y + s2.y + s3.y) * inv;
    r.z = (s0.z + s1.z + s2.z + s3.z) * inv;
    r.w = (s0.w + s1.w + s2.w + s3.w) * inv;
    *(float4*)&g_O[base] = r;
}

// ---------------------------------------------------------------------------
// Kernel 5: output projection, 64-row tiles for 2x grid (512 blocks).
// 128 threads, 4 rows x 8 cols per thread.  Same k0/kk summation order per
// output element as before -> bit-identical results.
// ---------------------------------------------------------------------------
__global__ __launch_bounds__(128) void outproj_kernel(const float* __restrict__ Wp,
                                                      const float* __restrict__ bp,
                                                      float* __restrict__ out) {
    __shared__ float As[64][33];
    __shared__ float Bs[64][33];
    int tid = threadIdx.x;
    int tx = tid & 7, ty = tid >> 3;      // ty 0..15
    int m0 = blockIdx.y * 64, n0 = blockIdx.x * 64;
    float acc[4][8] = {};
    for (int k0 = 0; k0 < Cc; k0 += 32) {
        int h = k0 >> 6;
#pragma unroll
        for (int l = tid; l < 512; l += 128) {
            int m = l >> 3, c = (l & 7) * 4;
            int mg = m0 + m;
            int bb = mg >> 11, nl = mg & (Nn - 1);
            int d = (k0 + c) & 63;
            float4 v = *(const float4*)&g_O[(((size_t)(bb * Hh + h)) * Nn + nl) * HD + d];
            As[m][c] = v.x; As[m][c + 1] = v.y; As[m][c + 2] = v.z; As[m][c + 3] = v.w;
        }
#pragma unroll
        for (int l = tid; l < 512; l += 128) {
            int n = l >> 3, c = (l & 7) * 4;
            float4 v = *(const float4*)&Wp[(size_t)(n0 + n) * Cc + k0 + c];
            Bs[n][c] = v.x; Bs[n][c + 1] = v.y; Bs[n][c + 2] = v.z; Bs[n][c + 3] = v.w;
        }
        __syncthreads();
#pragma unroll
        for (int kk = 0; kk < 32; kk++) {
            float a[4], b[8];
#pragma unroll
            for (int i = 0; i < 4; i++) a[i] = As[4 * ty + i][kk];
#pragma unroll
            for (int j = 0; j < 8; j++) b[j] = Bs[8 * tx + j][kk];
#pragma unroll
            for (int i = 0; i < 4; i++)
#pragma unroll
                for (int j = 0; j < 8; j++) acc[i][j] += a[i] * b[j];
        }
        __syncthreads();
    }
#pragma unroll
    for (int i = 0; i < 4; i++) {
        int m = m0 + 4 * ty + i;
#pragma unroll
        for (int j = 0; j < 8; j++) {
            int n = n0 + 8 * tx + j;
            out[(size_t)m * Cc + n] = acc[i][j] + bp[n];
        }
    }
}

// ---------------------------------------------------------------------------
extern "C" void kernel_launch(void* const* d_in, const int* in_sizes, int n_in,
                              void* d_out, int out_size) {
    (void)in_sizes; (void)n_in; (void)out_size;
    const float* q   = (const float*)d_in[0];
    const float* k_v = (const float*)d_in[1];
    const float* Wq  = (const float*)d_in[2];
    const float* Wk  = (const float*)d_in[3];
    const float* Wv  = (const float*)d_in[4];
    const float* Wp  = (const float*)d_in[5];
    const float* bp  = (const float*)d_in[6];
    float* out = (float*)d_out;

    dim3 gproj(Cc / 64, (Bb * Nn) / 128, 3);           // (8, 32, 3)
    proj_kernel<<<gproj, 128>>>(q, k_v, Wq, Wk, Wv);

    dim3 gqk(Nn / 32, Nn / 128, BH);                   // (64, 16, 16)
    qk_tc_kernel<<<gqk, 256>>>();

    select_kernel<<<BH * Nn, 256>>>();                 // 32768 paired blocks

    dim3 gspv(Nn / 128, JSPLIT, BH);                   // (16, 4, 16)
    spv_part_kernel<<<gspv, 128>>>();

    spv_merge_kernel<<<(BH * Nn * HD / 4) / 256, 256>>>();

    dim3 gout(Cc / 64, (Bb * Nn) / 64);                // (8, 64) = 512 blocks
    outproj_kernel<<<gout, 128>>>(Wp, bp, out);
}

// round 15
// speedup vs baseline: 1.0559x; 1.0141x over previous
#include <cuda_runtime.h>
#include <cstdint>

#define Bb   2
#define Nn   2048
#define Cc   512
#define Hh   8
#define HD   64
#define BH   16
#define KTOP 1024
#define SCALEF 0.125f
#define JSPLIT 4
#define JLEN  (Nn / JSPLIT)     // 512

// ---------------- scratch ----------------
__device__ float g_Qh[BH * Nn * HD];
__device__ float g_Kh[BH * Nn * HD];
__device__ float g_Vh[BH * Nn * HD];
__device__ float g_attn[(size_t)BH * Nn * Nn];
__device__ float g_attnT[(size_t)BH * Nn * Nn];
__device__ float g_rth[BH * Nn];
__device__ float g_cth[BH * Nn];
__device__ float g_rmax[BH * Nn];
__device__ float g_O[BH * Nn * HD];
__device__ float g_Opart[(size_t)JSPLIT * BH * Nn * HD];   // 32MB
__device__ float g_dpart[JSPLIT * BH * Nn];

// ---------------- tf32 helpers ----------------
__device__ __forceinline__ unsigned tf32_rna(float x) {
    unsigned u; asm("cvt.rna.tf32.f32 %0, %1;" : "=r"(u) : "f"(x)); return u;
}
__device__ __forceinline__ void split_tf32(float x, unsigned& hi, unsigned& lo) {
    hi = tf32_rna(x);
    float hf = __uint_as_float(hi);
    lo = tf32_rna(x - hf);
}
__device__ __forceinline__ void mma_tf32(float* c, const unsigned* a, const unsigned* b) {
    asm("mma.sync.aligned.m16n8k8.row.col.f32.tf32.tf32.f32 "
        "{%0,%1,%2,%3},{%4,%5,%6,%7},{%8,%9},{%0,%1,%2,%3};"
        : "+f"(c[0]), "+f"(c[1]), "+f"(c[2]), "+f"(c[3])
        : "r"(a[0]), "r"(a[1]), "r"(a[2]), "r"(a[3]), "r"(b[0]), "r"(b[1]));
}

// ---------------------------------------------------------------------------
// Kernel 1: ALL THREE projections in one launch (grid.z = which).  (R10 exact)
// ---------------------------------------------------------------------------
__global__ __launch_bounds__(128) void proj_kernel(const float* __restrict__ q,
                                                   const float* __restrict__ k_v,
                                                   const float* __restrict__ Wq,
                                                   const float* __restrict__ Wk,
                                                   const float* __restrict__ Wv) {
    __shared__ float As[128][33];
    __shared__ float Bs[64][33];
    int which = blockIdx.z;
    const float* X = (which == 0) ? q : k_v;
    const float* W = (which == 0) ? Wq : ((which == 1) ? Wk : Wv);
    int tid = threadIdx.x;
    int tx = tid & 7, ty = tid >> 3;
    int m0 = blockIdx.y * 128, n0 = blockIdx.x * 64;
    float acc[8][8] = {};
    for (int k0 = 0; k0 < Cc; k0 += 32) {
#pragma unroll
        for (int l = tid; l < 1024; l += 128) {
            int m = l >> 3, c = (l & 7) * 4;
            float4 v = *(const float4*)&X[(size_t)(m0 + m) * Cc + k0 + c];
            As[m][c] = v.x; As[m][c + 1] = v.y; As[m][c + 2] = v.z; As[m][c + 3] = v.w;
        }
#pragma unroll
        for (int l = tid; l < 512; l += 128) {
            int n = l >> 3, c = (l & 7) * 4;
            float4 v = *(const float4*)&W[(size_t)(n0 + n) * Cc + k0 + c];
            Bs[n][c] = v.x; Bs[n][c + 1] = v.y; Bs[n][c + 2] = v.z; Bs[n][c + 3] = v.w;
        }
        __syncthreads();
#pragma unroll
        for (int kk = 0; kk < 32; kk++) {
            float a[8], b[8];
#pragma unroll
            for (int i = 0; i < 8; i++) a[i] = As[8 * ty + i][kk];
#pragma unroll
            for (int j = 0; j < 8; j++) b[j] = Bs[8 * tx + j][kk];
#pragma unroll
            for (int i = 0; i < 8; i++)
#pragma unroll
                for (int j = 0; j < 8; j++) acc[i][j] += a[i] * b[j];
        }
        __syncthreads();
    }
    float* out = (which == 0) ? g_Qh : ((which == 1) ? g_Kh : g_Vh);
#pragma unroll
    for (int i = 0; i < 8; i++) {
        int m = m0 + 8 * ty + i;
        int bb = m >> 11, nl = m & (Nn - 1);
#pragma unroll
        for (int j = 0; j < 8; j++) {
            int n = n0 + 8 * tx + j;
            int h = n >> 6, d = n & 63;
            out[(((size_t)(bb * Hh + h)) * Nn + nl) * HD + d] = acc[i][j];
        }
    }
}

// ---------------------------------------------------------------------------
// Kernel 2: attn = scale * Q K^T via 3xTF32 mma.sync   (R4 exact)
// ---------------------------------------------------------------------------
__global__ __launch_bounds__(256) void qk_tc_kernel() {
    __shared__ float Qs[128][68];
    __shared__ float Ks[32][68];
    float (*Ts)[36] = (float(*)[36])Qs;

    int tid = threadIdx.x;
    int wid = tid >> 5, lane = tid & 31;
    int g = lane >> 2, t = lane & 3;
    int wm = wid & 3, wn = wid >> 2;
    int bh = blockIdx.z;
    int i0 = blockIdx.y * 128, j0 = blockIdx.x * 32;
    const float* Q = g_Qh + (size_t)bh * Nn * HD;
    const float* K = g_Kh + (size_t)bh * Nn * HD;

#pragma unroll
    for (int p = 0; p < 8; p++) {
        int idx = p * 256 + tid;
        int m = idx >> 4, c = (idx & 15) * 4;
        float4 v = *(const float4*)&Q[(size_t)(i0 + m) * HD + c];
        *(float4*)&Qs[m][c] = v;
    }
#pragma unroll
    for (int p = 0; p < 2; p++) {
        int idx = p * 256 + tid;
        int n = idx >> 4, c = (idx & 15) * 4;
        float4 v = *(const float4*)&K[(size_t)(j0 + n) * HD + c];
        *(float4*)&Ks[n][c] = v;
    }
    __syncthreads();

    float acc[2][2][4] = {};
#pragma unroll
    for (int ks = 0; ks < 8; ks++) {
        int k0 = ks * 8;
        unsigned ahi[2][4], alo[2][4], bhi[2][2], blo[2][2];
#pragma unroll
        for (int mt = 0; mt < 2; mt++) {
            int rb = 32 * wm + 16 * mt;
            float x0 = Qs[rb + g][k0 + t];
            float x1 = Qs[rb + g + 8][k0 + t];
            float x2 = Qs[rb + g][k0 + t + 4];
            float x3 = Qs[rb + g + 8][k0 + t + 4];
            split_tf32(x0, ahi[mt][0], alo[mt][0]);
            split_tf32(x1, ahi[mt][1], alo[mt][1]);
            split_tf32(x2, ahi[mt][2], alo[mt][2]);
            split_tf32(x3, ahi[mt][3], alo[mt][3]);
        }
#pragma unroll
        for (int nt = 0; nt < 2; nt++) {
            int nb = 16 * wn + 8 * nt;
            float y0 = Ks[nb + g][k0 + t];
            float y1 = Ks[nb + g][k0 + t + 4];
            split_tf32(y0, bhi[nt][0], blo[nt][0]);
            split_tf32(y1, bhi[nt][1], blo[nt][1]);
        }
#pragma unroll
        for (int mt = 0; mt < 2; mt++)
#pragma unroll
            for (int nt = 0; nt < 2; nt++) {
                mma_tf32(acc[mt][nt], ahi[mt], blo[nt]);
                mma_tf32(acc[mt][nt], alo[mt], bhi[nt]);
                mma_tf32(acc[mt][nt], ahi[mt], bhi[nt]);
            }
    }
    __syncthreads();

#pragma unroll
    for (int mt = 0; mt < 2; mt++)
#pragma unroll
        for (int nt = 0; nt < 2; nt++) {
            int r0 = 32 * wm + 16 * mt + g;
            int c0 = 16 * wn + 8 * nt + 2 * t;
            Ts[r0][c0]         = acc[mt][nt][0] * SCALEF;
            Ts[r0][c0 + 1]     = acc[mt][nt][1] * SCALEF;
            Ts[r0 + 8][c0]     = acc[mt][nt][2] * SCALEF;
            Ts[r0 + 8][c0 + 1] = acc[mt][nt][3] * SCALEF;
        }
    __syncthreads();

    float* attn = g_attn + ((size_t)bh * Nn + i0) * Nn + j0;
#pragma unroll
    for (int p = 0; p < 4; p++) {
        int idx = p * 256 + tid;
        int r = idx >> 3, cq = (idx & 7) * 4;
        *(float4*)&attn[(size_t)r * Nn + cq] = *(const float4*)&Ts[r][cq];
    }
    float* attnT = g_attnT + ((size_t)bh * Nn + j0) * Nn + i0;
#pragma unroll
    for (int p = 0; p < 16; p++) {
        int idx = p * 256 + tid;
        int jl = idx >> 7, il = idx & 127;
        attnT[(size_t)jl * Nn + il] = Ts[il][jl];
    }
}

// ---------------------------------------------------------------------------
// Kernel 3: PAIRED radix select   (R13 exact)
// ---------------------------------------------------------------------------
__global__ __launch_bounds__(256) void select_kernel() {
    __shared__ unsigned hist[2][2][256];
    __shared__ unsigned S[2][257];
    __shared__ unsigned s_selbin[2];
    __shared__ unsigned s_maxu;
    int tid = threadIdx.x;
    int sel = tid >> 7;           // 0: attn row, 1: attnT row
    int st  = tid & 127;
    int copy = (st >> 6) & 1;
    int lane = tid & 31;
    size_t row = blockIdx.x;
    const float* src = (sel ? g_attnT : g_attn) + row * Nn;

    unsigned u[16];
    unsigned lmax = 0u;
#pragma unroll
    for (int q = 0; q < 4; q++) {
        float4 v = *(const float4*)&src[st * 16 + 4 * q];
        float vals[4] = {v.x, v.y, v.z, v.w};
#pragma unroll
        for (int r = 0; r < 4; r++) {
            unsigned b = __float_as_uint(vals[r]);
            unsigned k = b ^ ((unsigned)((int)b >> 31) | 0x80000000u);
            u[4 * q + r] = k;
            lmax = lmax > k ? lmax : k;
        }
    }
    if (tid == 0) s_maxu = 0u;

    unsigned prefix = 0u;
    int krem = KTOP;
#pragma unroll
    for (int pass = 0; pass < 4; pass++) {
        int shift = 24 - 8 * pass;
#pragma unroll
        for (int i = tid; i < 1024; i += 256) ((unsigned*)hist)[i] = 0u;
        __syncthreads();
        if (pass == 0 && sel == 0) atomicMax(&s_maxu, lmax);
        unsigned himask = (pass == 0) ? 0u : (0xFFFFFFFFu << (shift + 8));
#pragma unroll
        for (int r = 0; r < 16; r++)
            if ((u[r] & himask) == prefix)
                atomicAdd(&hist[sel][copy][(u[r] >> shift) & 255u], 1u);
        __syncthreads();
        int wid = tid >> 5;
        if (wid == 0 || wid == 4) {
            int s = wid >> 2;
            int base = lane * 8;
            unsigned c[8], loc[8];
#pragma unroll
            for (int j = 0; j < 8; j++)
                c[j] = hist[s][0][base + j] + hist[s][1][base + j];
            loc[7] = c[7];
#pragma unroll
            for (int j = 6; j >= 0; j--) loc[j] = c[j] + loc[j + 1];
            unsigned T = loc[0], incl = T;
#pragma unroll
            for (int off = 1; off < 32; off <<= 1) {
                unsigned v = __shfl_down_sync(0xFFFFFFFFu, incl, off);
                if (lane + off < 32) incl += v;
            }
            unsigned excl = incl - T;
#pragma unroll
            for (int j = 0; j < 8; j++) S[s][base + j] = excl + loc[j];
            if (lane == 0) S[s][256] = 0u;
        }
        __syncthreads();
#pragma unroll
        for (int q = 0; q < 2; q++) {
            int b = 2 * st + q;
            unsigned St = S[sel][b], St1 = S[sel][b + 1];
            if ((int)St >= krem && (int)St1 < krem) s_selbin[sel] = (unsigned)b;
        }
        __syncthreads();
        unsigned selb = s_selbin[sel];
        krem -= (int)S[sel][selb + 1];
        prefix |= selb << shift;
        __syncthreads();
    }
    if (st == 0) {
        unsigned b = (prefix & 0x80000000u) ? (prefix ^ 0x80000000u) : ~prefix;
        float thr = __uint_as_float(b);
        if (sel) {
            g_cth[row] = thr;
        } else {
            g_rth[row] = thr;
            unsigned um = s_maxu;
            unsigned bm = (um & 0x80000000u) ? (um ^ 0x80000000u) : ~um;
            g_rmax[row] = __uint_as_float(bm);
        }
    }
}

// ---------------------------------------------------------------------------
// Kernel 4: fused masked softmax + P@V, J-SPLIT partials.
// REG-DIET v2 (race-free): no araw prefetch, and NO s_cth — each thread
// loads its own 4 column thresholds as one float4 LDG from g_cth (constant
// during this kernel; no shared producer, no ordering hazard).
// Per-element math and accumulation order identical to R13.
// grid (Nn/128, JSPLIT, BH), block 128, 4 blocks/SM.
// ---------------------------------------------------------------------------
__global__ __launch_bounds__(128, 4) void spv_part_kernel() {
    __shared__ float Ps[128][33];
    __shared__ float Vs[32][68];
    __shared__ float s_rth[128], s_mx[128], s_den[128];
    int tid = threadIdx.x;
    int tx = tid & 7, ty = tid >> 3;
    int bh = blockIdx.z;
    int part = blockIdx.y;
    int js = part * JLEN;
    int i0 = blockIdx.x * 128;
    const float* V = g_Vh + (size_t)bh * Nn * HD;
    const float* A = g_attn + ((size_t)bh * Nn + i0) * Nn;
    const float* CT = g_cth + bh * Nn;
    s_rth[tid] = g_rth[bh * Nn + i0 + tid];
    s_mx[tid]  = g_rmax[bh * Nn + i0 + tid];
    s_den[tid] = 0.f;
    __syncthreads();
    float rthr[8], mr[8], dloc[8];
#pragma unroll
    for (int i = 0; i < 8; i++) {
        rthr[i] = s_rth[8 * ty + i];
        mr[i]   = s_mx[8 * ty + i];
        dloc[i] = 0.f;
    }
    float acc[8][8] = {};

    for (int j0 = js; j0 < js + JLEN; j0 += 32) {
        __syncthreads();                  // prev chunk MMA done (Ps/Vs reusable)
#pragma unroll
        for (int l = tid; l < 512; l += 128) {
            int jl = l >> 4, d = (l & 15) * 4;
            *(float4*)&Vs[jl][d] = *(const float4*)&V[(size_t)(j0 + jl) * HD + d];
        }
        // per-thread column thresholds: one aligned float4 from gmem
        float4 ct4 = *(const float4*)&CT[j0 + 4 * tx];
        float cthv[4] = {ct4.x, ct4.y, ct4.z, ct4.w};
        // A loaded directly (8 independent LDG.128s)
#pragma unroll
        for (int i = 0; i < 8; i++) {
            float4 av4 = *(const float4*)&A[(size_t)(8 * ty + i) * Nn + j0 + 4 * tx];
            float av[4] = {av4.x, av4.y, av4.z, av4.w};
#pragma unroll
            for (int uu = 0; uu < 4; uu++) {
                float a = av[uu];
                float thr = fminf(rthr[i], cthv[uu]);
                float p = (a >= thr) ? __expf(a - mr[i]) : 0.f;
                dloc[i] += p;
                Ps[8 * ty + i][4 * tx + uu] = p;
            }
        }
        __syncthreads();                  // Vs + Ps visible
#pragma unroll
        for (int kk = 0; kk < 32; kk++) {
            float a[8], b[8];
#pragma unroll
            for (int i = 0; i < 8; i++) a[i] = Ps[8 * ty + i][kk];
            float4 b0 = *(const float4*)&Vs[kk][8 * tx];
            float4 b1 = *(const float4*)&Vs[kk][8 * tx + 4];
            b[0] = b0.x; b[1] = b0.y; b[2] = b0.z; b[3] = b0.w;
            b[4] = b1.x; b[5] = b1.y; b[6] = b1.z; b[7] = b1.w;
#pragma unroll
            for (int i = 0; i < 8; i++)
#pragma unroll
                for (int j = 0; j < 8; j++) acc[i][j] += a[i] * b[j];
        }
    }
#pragma unroll
    for (int i = 0; i < 8; i++) atomicAdd(&s_den[8 * ty + i], dloc[i]);
    __syncthreads();
    {
        size_t rowg = (size_t)bh * Nn + i0 + tid;
        g_dpart[(size_t)part * BH * Nn + rowg] = s_den[tid];
    }
    float* Op = g_Opart + (size_t)part * BH * Nn * HD;
#pragma unroll
    for (int i = 0; i < 8; i++) {
        int il = 8 * ty + i;
        float4 v0 = make_float4(acc[i][0], acc[i][1], acc[i][2], acc[i][3]);
        float4 v1 = make_float4(acc[i][4], acc[i][5], acc[i][6], acc[i][7]);
        float* o = &Op[((size_t)bh * Nn + i0 + il) * HD + 8 * tx];
        *(float4*)o = v0;
        *(float4*)(o + 4) = v1;
    }
}

// ---------------------------------------------------------------------------
// Kernel 4b: merge partials -> g_O.  (R10 exact)
// ---------------------------------------------------------------------------
__global__ __launch_bounds__(256) void spv_merge_kernel() {
    int gid = blockIdx.x * 256 + threadIdx.x;
    size_t row = (size_t)gid >> 4;
    int dd = (gid & 15) * 4;
    float den = g_dpart[row] + g_dpart[BH * Nn + row]
              + g_dpart[2 * BH * Nn + row] + g_dpart[3 * BH * Nn + row];
    float inv = 1.f / den;
    size_t base = row * HD + dd;
    float4 s0 = *(const float4*)&g_Opart[base];
    float4 s1 = *(const float4*)&g_Opart[(size_t)BH * Nn * HD + base];
    float4 s2 = *(const float4*)&g_Opart[2 * (size_t)BH * Nn * HD + base];
    float4 s3 = *(const float4*)&g_Opart[3 * (size_t)BH * Nn * HD + base];
    float4 r;
    r.x = (s0.x + s1.x + s2.x + s3.x) * inv;
    r.y = (s0.y + s1.y + s2.y + s3.y) * inv;
    r.z = (s0.z + s1.z + s2.z + s3.z) * inv;
    r.w = (s0.w + s1.w + s2.w + s3.w) * inv;
    *(float4*)&g_O[base] = r;
}

// ---------------------------------------------------------------------------
// Kernel 5: output projection, 64-row tiles (512 blocks).  (R13 exact)
// ---------------------------------------------------------------------------
__global__ __launch_bounds__(128) void outproj_kernel(const float* __restrict__ Wp,
                                                      const float* __restrict__ bp,
                                                      float* __restrict__ out) {
    __shared__ float As[64][33];
    __shared__ float Bs[64][33];
    int tid = threadIdx.x;
    int tx = tid & 7, ty = tid >> 3;      // ty 0..15
    int m0 = blockIdx.y * 64, n0 = blockIdx.x * 64;
    float acc[4][8] = {};
    for (int k0 = 0; k0 < Cc; k0 += 32) {
        int h = k0 >> 6;
#pragma unroll
        for (int l = tid; l < 512; l += 128) {
            int m = l >> 3, c = (l & 7) * 4;
            int mg = m0 + m;
            int bb = mg >> 11, nl = mg & (Nn - 1);
            int d = (k0 + c) & 63;
            float4 v = *(const float4*)&g_O[(((size_t)(bb * Hh + h)) * Nn + nl) * HD + d];
            As[m][c] = v.x; As[m][c + 1] = v.y; As[m][c + 2] = v.z; As[m][c + 3] = v.w;
        }
#pragma unroll
        for (int l = tid; l < 512; l += 128) {
            int n = l >> 3, c = (l & 7) * 4;
            float4 v = *(const float4*)&Wp[(size_t)(n0 + n) * Cc + k0 + c];
            Bs[n][c] = v.x; Bs[n][c + 1] = v.y; Bs[n][c + 2] = v.z; Bs[n][c + 3] = v.w;
        }
        __syncthreads();
#pragma unroll
        for (int kk = 0; kk < 32; kk++) {
            float a[4], b[8];
#pragma unroll
            for (int i = 0; i < 4; i++) a[i] = As[4 * ty + i][kk];
#pragma unroll
            for (int j = 0; j < 8; j++) b[j] = Bs[8 * tx + j][kk];
#pragma unroll
            for (int i = 0; i < 4; i++)
#pragma unroll
                for (int j = 0; j < 8; j++) acc[i][j] += a[i] * b[j];
        }
        __syncthreads();
    }
#pragma unroll
    for (int i = 0; i < 4; i++) {
        int m = m0 + 4 * ty + i;
#pragma unroll
        for (int j = 0; j < 8; j++) {
            int n = n0 + 8 * tx + j;
            out[(size_t)m * Cc + n] = acc[i][j] + bp[n];
        }
    }
}

// ---------------------------------------------------------------------------
extern "C" void kernel_launch(void* const* d_in, const int* in_sizes, int n_in,
                              void* d_out, int out_size) {
    (void)in_sizes; (void)n_in; (void)out_size;
    const float* q   = (const float*)d_in[0];
    const float* k_v = (const float*)d_in[1];
    const float* Wq  = (const float*)d_in[2];
    const float* Wk  = (const float*)d_in[3];
    const float* Wv  = (const float*)d_in[4];
    const float* Wp  = (const float*)d_in[5];
    const float* bp  = (const float*)d_in[6];
    float* out = (float*)d_out;

    dim3 gproj(Cc / 64, (Bb * Nn) / 128, 3);           // (8, 32, 3)
    proj_kernel<<<gproj, 128>>>(q, k_v, Wq, Wk, Wv);

    dim3 gqk(Nn / 32, Nn / 128, BH);                   // (64, 16, 16)
    qk_tc_kernel<<<gqk, 256>>>();

    select_kernel<<<BH * Nn, 256>>>();                 // 32768 paired blocks

    dim3 gspv(Nn / 128, JSPLIT, BH);                   // (16, 4, 16)
    spv_part_kernel<<<gspv, 128>>>();

    spv_merge_kernel<<<(BH * Nn * HD / 4) / 256, 256>>>();

    dim3 gout(Cc / 64, (Bb * Nn) / 64);                // (8, 64) = 512 blocks
    outproj_kernel<<<gout, 128>>>(Wp, bp, out);
}

// round 16
// speedup vs baseline: 1.0697x; 1.0130x over previous
#include <cuda_runtime.h>
#include <cstdint>

#define Bb   2
#define Nn   2048
#define Cc   512
#define Hh   8
#define HD   64
#define BH   16
#define KTOP 1024
#define SCALEF 0.125f
#define JSPLIT 4
#define JLEN  (Nn / JSPLIT)     // 512

// ---------------- scratch ----------------
__device__ float g_Qh[BH * Nn * HD];
__device__ float g_Kh[BH * Nn * HD];
__device__ float g_Vh[BH * Nn * HD];
__device__ float g_attn[(size_t)BH * Nn * Nn];
__device__ float g_attnT[(size_t)BH * Nn * Nn];
__device__ float g_rth[BH * Nn];
__device__ float g_cth[BH * Nn];
__device__ float g_rmax[BH * Nn];
__device__ float g_O[BH * Nn * HD];
__device__ float g_Opart[(size_t)JSPLIT * BH * Nn * HD];   // 32MB
__device__ float g_dpart[JSPLIT * BH * Nn];

// ---------------- tf32 helpers ----------------
__device__ __forceinline__ unsigned tf32_rna(float x) {
    unsigned u; asm("cvt.rna.tf32.f32 %0, %1;" : "=r"(u) : "f"(x)); return u;
}
__device__ __forceinline__ void split_tf32(float x, unsigned& hi, unsigned& lo) {
    hi = tf32_rna(x);
    float hf = __uint_as_float(hi);
    lo = tf32_rna(x - hf);
}
__device__ __forceinline__ void mma_tf32(float* c, const unsigned* a, const unsigned* b) {
    asm("mma.sync.aligned.m16n8k8.row.col.f32.tf32.tf32.f32 "
        "{%0,%1,%2,%3},{%4,%5,%6,%7},{%8,%9},{%0,%1,%2,%3};"
        : "+f"(c[0]), "+f"(c[1]), "+f"(c[2]), "+f"(c[3])
        : "r"(a[0]), "r"(a[1]), "r"(a[2]), "r"(a[3]), "r"(b[0]), "r"(b[1]));
}

// ---------------------------------------------------------------------------
// Kernel 1: ALL THREE projections in one launch (grid.z = which).  (R10 exact)
// ---------------------------------------------------------------------------
__global__ __launch_bounds__(128) void proj_kernel(const float* __restrict__ q,
                                                   const float* __restrict__ k_v,
                                                   const float* __restrict__ Wq,
                                                   const float* __restrict__ Wk,
                                                   const float* __restrict__ Wv) {
    __shared__ float As[128][33];
    __shared__ float Bs[64][33];
    int which = blockIdx.z;
    const float* X = (which == 0) ? q : k_v;
    const float* W = (which == 0) ? Wq : ((which == 1) ? Wk : Wv);
    int tid = threadIdx.x;
    int tx = tid & 7, ty = tid >> 3;
    int m0 = blockIdx.y * 128, n0 = blockIdx.x * 64;
    float acc[8][8] = {};
    for (int k0 = 0; k0 < Cc; k0 += 32) {
#pragma unroll
        for (int l = tid; l < 1024; l += 128) {
            int m = l >> 3, c = (l & 7) * 4;
            float4 v = *(const float4*)&X[(size_t)(m0 + m) * Cc + k0 + c];
            As[m][c] = v.x; As[m][c + 1] = v.y; As[m][c + 2] = v.z; As[m][c + 3] = v.w;
        }
#pragma unroll
        for (int l = tid; l < 512; l += 128) {
            int n = l >> 3, c = (l & 7) * 4;
            float4 v = *(const float4*)&W[(size_t)(n0 + n) * Cc + k0 + c];
            Bs[n][c] = v.x; Bs[n][c + 1] = v.y; Bs[n][c + 2] = v.z; Bs[n][c + 3] = v.w;
        }
        __syncthreads();
#pragma unroll
        for (int kk = 0; kk < 32; kk++) {
            float a[8], b[8];
#pragma unroll
            for (int i = 0; i < 8; i++) a[i] = As[8 * ty + i][kk];
#pragma unroll
            for (int j = 0; j < 8; j++) b[j] = Bs[8 * tx + j][kk];
#pragma unroll
            for (int i = 0; i < 8; i++)
#pragma unroll
                for (int j = 0; j < 8; j++) acc[i][j] += a[i] * b[j];
        }
        __syncthreads();
    }
    float* out = (which == 0) ? g_Qh : ((which == 1) ? g_Kh : g_Vh);
#pragma unroll
    for (int i = 0; i < 8; i++) {
        int m = m0 + 8 * ty + i;
        int bb = m >> 11, nl = m & (Nn - 1);
#pragma unroll
        for (int j = 0; j < 8; j++) {
            int n = n0 + 8 * tx + j;
            int h = n >> 6, d = n & 63;
            out[(((size_t)(bb * Hh + h)) * Nn + nl) * HD + d] = acc[i][j];
        }
    }
}

// ---------------------------------------------------------------------------
// Kernel 2: attn = scale * Q K^T via 3xTF32 mma.sync.
// RETILED: M=128 x N=64 per block (A-split work halves vs N=32), K chunks
// of 32 (Qs[128][36]+Ks[64][36] = 27.6KB).  Fragment banks (4g+t): conflict-
// free.  Epilogue stages 64 rows at a time in Ts[64][68] overlay (2 passes).
// Same split values + same k-order + same mma sequence -> attn bit-identical.
// grid (Nn/64, Nn/128, BH) = (32, 16, 16) = 8192 blocks, 256 thr.
// ---------------------------------------------------------------------------
__global__ __launch_bounds__(256) void qk_tc_kernel() {
    __shared__ float sm[128 * 36 + 64 * 36];     // 27.6KB
    float (*Qs)[36] = (float(*)[36])sm;
    float (*Ks)[36] = (float(*)[36])(sm + 128 * 36);
    float (*Ts)[68] = (float(*)[68])sm;          // 64x68 overlay (17.4KB)

    int tid = threadIdx.x;
    int wid = tid >> 5, lane = tid & 31;
    int g = lane >> 2, t = lane & 3;
    int wm = wid & 3, wn = wid >> 2;             // wm 0..3 (32 rows), wn 0..1 (32 cols)
    int bh = blockIdx.z;
    int i0 = blockIdx.y * 128, j0 = blockIdx.x * 64;
    const float* Q = g_Qh + (size_t)bh * Nn * HD;
    const float* K = g_Kh + (size_t)bh * Nn * HD;

    float acc[2][4][4] = {};                     // [mt][nt][frag]
#pragma unroll
    for (int kc = 0; kc < HD; kc += 32) {
#pragma unroll
        for (int p = 0; p < 4; p++) {            // Q chunk 128x32
            int idx = p * 256 + tid;
            int m = idx >> 3, c = (idx & 7) * 4;
            float4 v = *(const float4*)&Q[(size_t)(i0 + m) * HD + kc + c];
            *(float4*)&Qs[m][c] = v;
        }
#pragma unroll
        for (int p = 0; p < 2; p++) {            // K chunk 64x32
            int idx = p * 256 + tid;
            int n = idx >> 3, c = (idx & 7) * 4;
            float4 v = *(const float4*)&K[(size_t)(j0 + n) * HD + kc + c];
            *(float4*)&Ks[n][c] = v;
        }
        __syncthreads();
#pragma unroll
        for (int ks = 0; ks < 4; ks++) {
            int k0 = ks * 8;
            unsigned ahi[2][4], alo[2][4], bhi[4][2], blo[4][2];
#pragma unroll
            for (int mt = 0; mt < 2; mt++) {
                int rb = 32 * wm + 16 * mt;
                float x0 = Qs[rb + g][k0 + t];
                float x1 = Qs[rb + g + 8][k0 + t];
                float x2 = Qs[rb + g][k0 + t + 4];
                float x3 = Qs[rb + g + 8][k0 + t + 4];
                split_tf32(x0, ahi[mt][0], alo[mt][0]);
                split_tf32(x1, ahi[mt][1], alo[mt][1]);
                split_tf32(x2, ahi[mt][2], alo[mt][2]);
                split_tf32(x3, ahi[mt][3], alo[mt][3]);
            }
#pragma unroll
            for (int nt = 0; nt < 4; nt++) {
                int nb = 32 * wn + 8 * nt;
                float y0 = Ks[nb + g][k0 + t];
                float y1 = Ks[nb + g][k0 + t + 4];
                split_tf32(y0, bhi[nt][0], blo[nt][0]);
                split_tf32(y1, bhi[nt][1], blo[nt][1]);
            }
#pragma unroll
            for (int mt = 0; mt < 2; mt++)
#pragma unroll
                for (int nt = 0; nt < 4; nt++) {
                    mma_tf32(acc[mt][nt], ahi[mt], blo[nt]);
                    mma_tf32(acc[mt][nt], alo[mt], bhi[nt]);
                    mma_tf32(acc[mt][nt], ahi[mt], bhi[nt]);
                }
        }
        __syncthreads();
    }

    // epilogue: two 64-row passes through Ts overlay
#pragma unroll
    for (int pass = 0; pass < 2; pass++) {
        if ((wm >> 1) == pass) {
#pragma unroll
            for (int mt = 0; mt < 2; mt++)
#pragma unroll
                for (int nt = 0; nt < 4; nt++) {
                    int r0 = 32 * (wm & 1) + 16 * mt + g;   // local row 0..63
                    int c0 = 32 * wn + 8 * nt + 2 * t;
                    Ts[r0][c0]         = acc[mt][nt][0] * SCALEF;
                    Ts[r0][c0 + 1]     = acc[mt][nt][1] * SCALEF;
                    Ts[r0 + 8][c0]     = acc[mt][nt][2] * SCALEF;
                    Ts[r0 + 8][c0 + 1] = acc[mt][nt][3] * SCALEF;
                }
        }
        __syncthreads();
        float* attn = g_attn + ((size_t)bh * Nn + i0 + 64 * pass) * Nn + j0;
#pragma unroll
        for (int p = 0; p < 4; p++) {            // 64x64 floats as float4
            int idx = p * 256 + tid;
            int r = idx >> 4, cq = (idx & 15) * 4;
            *(float4*)&attn[(size_t)r * Nn + cq] = *(const float4*)&Ts[r][cq];
        }
        float* attnT = g_attnT + ((size_t)bh * Nn + j0) * Nn + i0 + 64 * pass;
#pragma unroll
        for (int p = 0; p < 16; p++) {           // 64 cols x 64 rows scalar
            int idx = p * 256 + tid;
            int jl = idx >> 6, il = idx & 63;
            attnT[(size_t)jl * Nn + il] = Ts[il][jl];
        }
        __syncthreads();                          // before next pass reuses Ts
    }
}

// ---------------------------------------------------------------------------
// Kernel 3: PAIRED radix select   (R13 exact)
// ---------------------------------------------------------------------------
__global__ __launch_bounds__(256) void select_kernel() {
    __shared__ unsigned hist[2][2][256];
    __shared__ unsigned S[2][257];
    __shared__ unsigned s_selbin[2];
    __shared__ unsigned s_maxu;
    int tid = threadIdx.x;
    int sel = tid >> 7;           // 0: attn row, 1: attnT row
    int st  = tid & 127;
    int copy = (st >> 6) & 1;
    int lane = tid & 31;
    size_t row = blockIdx.x;
    const float* src = (sel ? g_attnT : g_attn) + row * Nn;

    unsigned u[16];
    unsigned lmax = 0u;
#pragma unroll
    for (int q = 0; q < 4; q++) {
        float4 v = *(const float4*)&src[st * 16 + 4 * q];
        float vals[4] = {v.x, v.y, v.z, v.w};
#pragma unroll
        for (int r = 0; r < 4; r++) {
            unsigned b = __float_as_uint(vals[r]);
            unsigned k = b ^ ((unsigned)((int)b >> 31) | 0x80000000u);
            u[4 * q + r] = k;
            lmax = lmax > k ? lmax : k;
        }
    }
    if (tid == 0) s_maxu = 0u;

    unsigned prefix = 0u;
    int krem = KTOP;
#pragma unroll
    for (int pass = 0; pass < 4; pass++) {
        int shift = 24 - 8 * pass;
#pragma unroll
        for (int i = tid; i < 1024; i += 256) ((unsigned*)hist)[i] = 0u;
        __syncthreads();
        if (pass == 0 && sel == 0) atomicMax(&s_maxu, lmax);
        unsigned himask = (pass == 0) ? 0u : (0xFFFFFFFFu << (shift + 8));
#pragma unroll
        for (int r = 0; r < 16; r++)
            if ((u[r] & himask) == prefix)
                atomicAdd(&hist[sel][copy][(u[r] >> shift) & 255u], 1u);
        __syncthreads();
        int wid = tid >> 5;
        if (wid == 0 || wid == 4) {
            int s = wid >> 2;
            int base = lane * 8;
            unsigned c[8], loc[8];
#pragma unroll
            for (int j = 0; j < 8; j++)
                c[j] = hist[s][0][base + j] + hist[s][1][base + j];
            loc[7] = c[7];
#pragma unroll
            for (int j = 6; j >= 0; j--) loc[j] = c[j] + loc[j + 1];
            unsigned T = loc[0], incl = T;
#pragma unroll
            for (int off = 1; off < 32; off <<= 1) {
                unsigned v = __shfl_down_sync(0xFFFFFFFFu, incl, off);
                if (lane + off < 32) incl += v;
            }
            unsigned excl = incl - T;
#pragma unroll
            for (int j = 0; j < 8; j++) S[s][base + j] = excl + loc[j];
            if (lane == 0) S[s][256] = 0u;
        }
        __syncthreads();
#pragma unroll
        for (int q = 0; q < 2; q++) {
            int b = 2 * st + q;
            unsigned St = S[sel][b], St1 = S[sel][b + 1];
            if ((int)St >= krem && (int)St1 < krem) s_selbin[sel] = (unsigned)b;
        }
        __syncthreads();
        unsigned selb = s_selbin[sel];
        krem -= (int)S[sel][selb + 1];
        prefix |= selb << shift;
        __syncthreads();
    }
    if (st == 0) {
        unsigned b = (prefix & 0x80000000u) ? (prefix ^ 0x80000000u) : ~prefix;
        float thr = __uint_as_float(b);
        if (sel) {
            g_cth[row] = thr;
        } else {
            g_rth[row] = thr;
            unsigned um = s_maxu;
            unsigned bm = (um & 0x80000000u) ? (um ^ 0x80000000u) : ~um;
            g_rmax[row] = __uint_as_float(bm);
        }
    }
}

// ---------------------------------------------------------------------------
// Kernel 4: fused masked softmax + P@V, J-SPLIT partials.  (R15 exact)
// grid (Nn/128, JSPLIT, BH), block 128, 4 blocks/SM.
// ---------------------------------------------------------------------------
__global__ __launch_bounds__(128, 4) void spv_part_kernel() {
    __shared__ float Ps[128][33];
    __shared__ float Vs[32][68];
    __shared__ float s_rth[128], s_mx[128], s_den[128];
    int tid = threadIdx.x;
    int tx = tid & 7, ty = tid >> 3;
    int bh = blockIdx.z;
    int part = blockIdx.y;
    int js = part * JLEN;
    int i0 = blockIdx.x * 128;
    const float* V = g_Vh + (size_t)bh * Nn * HD;
    const float* A = g_attn + ((size_t)bh * Nn + i0) * Nn;
    const float* CT = g_cth + bh * Nn;
    s_rth[tid] = g_rth[bh * Nn + i0 + tid];
    s_mx[tid]  = g_rmax[bh * Nn + i0 + tid];
    s_den[tid] = 0.f;
    __syncthreads();
    float rthr[8], mr[8], dloc[8];
#pragma unroll
    for (int i = 0; i < 8; i++) {
        rthr[i] = s_rth[8 * ty + i];
        mr[i]   = s_mx[8 * ty + i];
        dloc[i] = 0.f;
    }
    float acc[8][8] = {};

    for (int j0 = js; j0 < js + JLEN; j0 += 32) {
        __syncthreads();
#pragma unroll
        for (int l = tid; l < 512; l += 128) {
            int jl = l >> 4, d = (l & 15) * 4;
            *(float4*)&Vs[jl][d] = *(const float4*)&V[(size_t)(j0 + jl) * HD + d];
        }
        float4 ct4 = *(const float4*)&CT[j0 + 4 * tx];
        float cthv[4] = {ct4.x, ct4.y, ct4.z, ct4.w};
#pragma unroll
        for (int i = 0; i < 8; i++) {
            float4 av4 = *(const float4*)&A[(size_t)(8 * ty + i) * Nn + j0 + 4 * tx];
            float av[4] = {av4.x, av4.y, av4.z, av4.w};
#pragma unroll
            for (int uu = 0; uu < 4; uu++) {
                float a = av[uu];
                float thr = fminf(rthr[i], cthv[uu]);
                float p = (a >= thr) ? __expf(a - mr[i]) : 0.f;
                dloc[i] += p;
                Ps[8 * ty + i][4 * tx + uu] = p;
            }
        }
        __syncthreads();
#pragma unroll
        for (int kk = 0; kk < 32; kk++) {
            float a[8], b[8];
#pragma unroll
            for (int i = 0; i < 8; i++) a[i] = Ps[8 * ty + i][kk];
            float4 b0 = *(const float4*)&Vs[kk][8 * tx];
            float4 b1 = *(const float4*)&Vs[kk][8 * tx + 4];
            b[0] = b0.x; b[1] = b0.y; b[2] = b0.z; b[3] = b0.w;
            b[4] = b1.x; b[5] = b1.y; b[6] = b1.z; b[7] = b1.w;
#pragma unroll
            for (int i = 0; i < 8; i++)
#pragma unroll
                for (int j = 0; j < 8; j++) acc[i][j] += a[i] * b[j];
        }
    }
#pragma unroll
    for (int i = 0; i < 8; i++) atomicAdd(&s_den[8 * ty + i], dloc[i]);
    __syncthreads();
    {
        size_t rowg = (size_t)bh * Nn + i0 + tid;
        g_dpart[(size_t)part * BH * Nn + rowg] = s_den[tid];
    }
    float* Op = g_Opart + (size_t)part * BH * Nn * HD;
#pragma unroll
    for (int i = 0; i < 8; i++) {
        int il = 8 * ty + i;
        float4 v0 = make_float4(acc[i][0], acc[i][1], acc[i][2], acc[i][3]);
        float4 v1 = make_float4(acc[i][4], acc[i][5], acc[i][6], acc[i][7]);
        float* o = &Op[((size_t)bh * Nn + i0 + il) * HD + 8 * tx];
        *(float4*)o = v0;
        *(float4*)(o + 4) = v1;
    }
}

// ---------------------------------------------------------------------------
// Kernel 4b: merge partials -> g_O.  (R10 exact)
// ---------------------------------------------------------------------------
__global__ __launch_bounds__(256) void spv_merge_kernel() {
    int gid = blockIdx.x * 256 + threadIdx.x;
    size_t row = (size_t)gid >> 4;
    int dd = (gid & 15) * 4;
    float den = g_dpart[row] + g_dpart[BH * Nn + row]
              + g_dpart[2 * BH * Nn + row] + g_dpart[3 * BH * Nn + row];
    float inv = 1.f / den;
    size_t base = row * HD + dd;
    float4 s0 = *(const float4*)&g_Opart[base];
    float4 s1 = *(const float4*)&g_Opart[(size_t)BH * Nn * HD + base];
    float4 s2 = *(const float4*)&g_Opart[2 * (size_t)BH * Nn * HD + base];
    float4 s3 = *(const float4*)&g_Opart[3 * (size_t)BH * Nn * HD + base];
    float4 r;
    r.x = (s0.x + s1.x + s2.x + s3.x) * inv;
    r.y = (s0.y + s1.y + s2.y + s3.y) * inv;
    r.z = (s0.z + s1.z + s2.z + s3.z) * inv;
    r.w = (s0.w + s1.w + s2.w + s3.w) * inv;
    *(float4*)&g_O[base] = r;
}

// ---------------------------------------------------------------------------
// Kernel 5: output projection, 64-row tiles (512 blocks).  (R13 exact)
// ---------------------------------------------------------------------------
__global__ __launch_bounds__(128) void outproj_kernel(const float* __restrict__ Wp,
                                                      const float* __restrict__ bp,
                                                      float* __restrict__ out) {
    __shared__ float As[64][33];
    __shared__ float Bs[64][33];
    int tid = threadIdx.x;
    int tx = tid & 7, ty = tid >> 3;      // ty 0..15
    int m0 = blockIdx.y * 64, n0 = blockIdx.x * 64;
    float acc[4][8] = {};
    for (int k0 = 0; k0 < Cc; k0 += 32) {
        int h = k0 >> 6;
#pragma unroll
        for (int l = tid; l < 512; l += 128) {
            int m = l >> 3, c = (l & 7) * 4;
            int mg = m0 + m;
            int bb = mg >> 11, nl = mg & (Nn - 1);
            int d = (k0 + c) & 63;
            float4 v = *(const float4*)&g_O[(((size_t)(bb * Hh + h)) * Nn + nl) * HD + d];
            As[m][c] = v.x; As[m][c + 1] = v.y; As[m][c + 2] = v.z; As[m][c + 3] = v.w;
        }
#pragma unroll
        for (int l = tid; l < 512; l += 128) {
            int n = l >> 3, c = (l & 7) * 4;
            float4 v = *(const float4*)&Wp[(size_t)(n0 + n) * Cc + k0 + c];
            Bs[n][c] = v.x; Bs[n][c + 1] = v.y; Bs[n][c + 2] = v.z; Bs[n][c + 3] = v.w;
        }
        __syncthreads();
#pragma unroll
        for (int kk = 0; kk < 32; kk++) {
            float a[4], b[8];
#pragma unroll
            for (int i = 0; i < 4; i++) a[i] = As[4 * ty + i][kk];
#pragma unroll
            for (int j = 0; j < 8; j++) b[j] = Bs[8 * tx + j][kk];
#pragma unroll
            for (int i = 0; i < 4; i++)
#pragma unroll
                for (int j = 0; j < 8; j++) acc[i][j] += a[i] * b[j];
        }
        __syncthreads();
    }
#pragma unroll
    for (int i = 0; i < 4; i++) {
        int m = m0 + 4 * ty + i;
#pragma unroll
        for (int j = 0; j < 8; j++) {
            int n = n0 + 8 * tx + j;
            out[(size_t)m * Cc + n] = acc[i][j] + bp[n];
        }
    }
}

// ---------------------------------------------------------------------------
extern "C" void kernel_launch(void* const* d_in, const int* in_sizes, int n_in,
                              void* d_out, int out_size) {
    (void)in_sizes; (void)n_in; (void)out_size;
    const float* q   = (const float*)d_in[0];
    const float* k_v = (const float*)d_in[1];
    const float* Wq  = (const float*)d_in[2];
    const float* Wk  = (const float*)d_in[3];
    const float* Wv  = (const float*)d_in[4];
    const float* Wp  = (const float*)d_in[5];
    const float* bp  = (const float*)d_in[6];
    float* out = (float*)d_out;

    dim3 gproj(Cc / 64, (Bb * Nn) / 128, 3);           // (8, 32, 3)
    proj_kernel<<<gproj, 128>>>(q, k_v, Wq, Wk, Wv);

    dim3 gqk(Nn / 64, Nn / 128, BH);                   // (32, 16, 16) = 8192 blocks
    qk_tc_kernel<<<gqk, 256>>>();

    select_kernel<<<BH * Nn, 256>>>();                 // 32768 paired blocks

    dim3 gspv(Nn / 128, JSPLIT, BH);                   // (16, 4, 16)
    spv_part_kernel<<<gspv, 128>>>();

    spv_merge_kernel<<<(BH * Nn * HD / 4) / 256, 256>>>();

    dim3 gout(Cc / 64, (Bb * Nn) / 64);                // (8, 64) = 512 blocks
    outproj_kernel<<<gout, 128>>>(Wp, bp, out);
}